// round 11
// baseline (speedup 1.0000x reference)
#include <cuda_runtime.h>
#include <cuda_bf16.h>
#include <cstdint>
#include <cstddef>

#define T_DIM 2048
#define B_DIM 2
#define E_DIM 1024
#define H_DIM 16
#define MROWS (T_DIM * B_DIM)      // 4096
#define K_DIM 1024
#define NEG_INF_F (-1e24f)

// ---------------------------------------------------------------------------
// Scratch (no cudaMalloc allowed)
// ---------------------------------------------------------------------------
__device__ __nv_bfloat16 g_x_hi[(size_t)MROWS * E_DIM];
__device__ __nv_bfloat16 g_x_lo[(size_t)MROWS * E_DIM];
__device__ __nv_bfloat16 g_win_hi[(size_t)3 * E_DIM * E_DIM];
__device__ __nv_bfloat16 g_win_lo[(size_t)3 * E_DIM * E_DIM];
__device__ __nv_bfloat16 g_wout_hi[(size_t)E_DIM * E_DIM];
__device__ __nv_bfloat16 g_wout_lo[(size_t)E_DIM * E_DIM];
__device__ __nv_bfloat16 g_q_hi[(size_t)MROWS * E_DIM];
__device__ __nv_bfloat16 g_q_lo[(size_t)MROWS * E_DIM];
// compacted K|V: row = b*2048 + compact_j, cols [0,1024)=K, [1024,2048)=V
__device__ __nv_bfloat16 g_kv_hi[(size_t)MROWS * 2 * E_DIM];
__device__ __nv_bfloat16 g_kv_lo[(size_t)MROWS * 2 * E_DIM];
__device__ __nv_bfloat16 g_attn_hi[(size_t)MROWS * E_DIM];
__device__ __nv_bfloat16 g_attn_lo[(size_t)MROWS * E_DIM];
__device__ unsigned char g_mask[MROWS];
__device__ int   g_kidx[B_DIM * T_DIM];
__device__ int   g_kcount[B_DIM];
__device__ float g_kmask[B_DIM * T_DIM];

// ===========================================================================
// PTX helpers
// ===========================================================================
__device__ __forceinline__ uint32_t smem_u32(const void* p) {
    uint32_t a;
    asm("{ .reg .u64 t; cvta.to.shared.u64 t, %1; cvt.u32.u64 %0, t; }"
        : "=r"(a) : "l"(p));
    return a;
}
__device__ __forceinline__ void ldmatrix_x4(uint32_t& r0, uint32_t& r1,
                                            uint32_t& r2, uint32_t& r3,
                                            uint32_t addr) {
    asm volatile("ldmatrix.sync.aligned.m8n8.x4.shared.b16 {%0,%1,%2,%3}, [%4];"
                 : "=r"(r0), "=r"(r1), "=r"(r2), "=r"(r3) : "r"(addr));
}
__device__ __forceinline__ void ldmatrix_x4_trans(uint32_t& r0, uint32_t& r1,
                                                  uint32_t& r2, uint32_t& r3,
                                                  uint32_t addr) {
    asm volatile("ldmatrix.sync.aligned.m8n8.x4.trans.shared.b16 {%0,%1,%2,%3}, [%4];"
                 : "=r"(r0), "=r"(r1), "=r"(r2), "=r"(r3) : "r"(addr));
}
__device__ __forceinline__ void mma_bf16(float* d, const uint32_t* a,
                                         const uint32_t* b) {
    asm("mma.sync.aligned.m16n8k16.row.col.f32.bf16.bf16.f32 "
        "{%0,%1,%2,%3}, {%4,%5,%6,%7}, {%8,%9}, {%0,%1,%2,%3};"
        : "+f"(d[0]), "+f"(d[1]), "+f"(d[2]), "+f"(d[3])
        : "r"(a[0]), "r"(a[1]), "r"(a[2]), "r"(a[3]), "r"(b[0]), "r"(b[1]));
}
__device__ __forceinline__ void cp_async16(uint32_t dst, const void* src) {
    asm volatile("cp.async.cg.shared.global [%0], [%1], 16;" :: "r"(dst), "l"(src));
}
__device__ __forceinline__ void cp_commit() {
    asm volatile("cp.async.commit_group;" ::: "memory");
}
template<int N> __device__ __forceinline__ void cp_wait() {
    asm volatile("cp.async.wait_group %0;" :: "n"(N) : "memory");
}

__device__ __forceinline__ void split2(float x, float y,
                                       uint32_t& hi, uint32_t& lo) {
    __nv_bfloat16 hx = __float2bfloat16(x);
    __nv_bfloat16 hy = __float2bfloat16(y);
    __nv_bfloat16 lx = __float2bfloat16(x - __bfloat162float(hx));
    __nv_bfloat16 ly = __float2bfloat16(y - __bfloat162float(hy));
    __nv_bfloat162 hp = __halves2bfloat162(hx, hy);
    __nv_bfloat162 lp = __halves2bfloat162(lx, ly);
    hi = *(uint32_t*)&hp;
    lo = *(uint32_t*)&lp;
}

// ===========================================================================
// Mask prep (single kernel, single block): detect dtype, expand, compact.
// ===========================================================================
__global__ void mask_prep_kernel(const void* __restrict__ mv)
{
    const unsigned char* m8 = (const unsigned char*)mv;
    __shared__ int s_nz, s_f32;
    int tid = threadIdx.x;
    if (tid == 0) { s_nz = 0; s_f32 = 0; }
    __syncthreads();
    int nz = 0, f32 = 0;
    for (int i = tid; i < MROWS; i += 256) {
        unsigned char v = m8[i];
        if ((i & 3) != 0 && v != 0) nz = 1;
        if ((i & 3) == 3 && v == 0x3F) f32 = 1;
    }
    if (nz)  atomicOr(&s_nz, 1);
    if (f32) atomicOr(&s_f32, 1);
    __syncthreads();
    int mode = s_f32 ? 2 : (s_nz ? 0 : 1);
    for (int i = tid; i < MROWS; i += 256) {
        unsigned char r;
        if (mode == 0)      r = m8[i] != 0;
        else if (mode == 1) r = ((const int*)mv)[i] != 0;
        else                r = ((const float*)mv)[i] != 0.0f;
        g_mask[i] = r;
    }
    __syncthreads();
    if (tid < 64) {
        int b = tid >> 5, lane = tid & 31;
        int base = 0;
        for (int j0 = 0; j0 < T_DIM; j0 += 32) {
            int t = j0 + lane;
            int keep = g_mask[t * B_DIM + b] ? 0 : 1;
            unsigned bal = __ballot_sync(0xffffffffu, keep);
            int pre = __popc(bal & ((1u << lane) - 1));
            if (keep) g_kidx[b * T_DIM + base + pre] = t;
            base += __popc(bal);
        }
        if (lane == 0) g_kcount[b] = base;
        for (int j = base + lane; j < T_DIM; j += 32)
            g_kidx[b * T_DIM + j] = 0;
        for (int j = lane; j < T_DIM; j += 32)
            g_kmask[b * T_DIM + j] = (j < base) ? 0.f : NEG_INF_F;
    }
}

// ===========================================================================
// Pre-split fp32 -> bf16 hi/lo
// ===========================================================================
__global__ void presplit_kernel(const float* __restrict__ src,
                                __nv_bfloat16* __restrict__ hi,
                                __nv_bfloat16* __restrict__ lo, int n4)
{
    int i = blockIdx.x * 256 + threadIdx.x;
    if (i >= n4) return;
    float4 v = ((const float4*)src)[i];
    uint32_t h0, l0, h1, l1;
    split2(v.x, v.y, h0, l0);
    split2(v.z, v.w, h1, l1);
    uint2 hh, ll;
    hh.x = h0; hh.y = h1;
    ll.x = l0; ll.y = l1;
    ((uint2*)hi)[i] = hh;
    ((uint2*)lo)[i] = ll;
}

// ===========================================================================
// 2-stage pipelined split-bf16 HMMA GEMM (dense rows)
// ===========================================================================
#define GST   55296
#define G_AH  0
#define G_AL  18432
#define G_BH  36864
#define G_BL  46080
#define G_TOTAL (2 * GST)
#define G_RM  G_TOTAL
#define G_TOTAL_KV (G_TOTAL + 512)

template<bool SPLIT_OUT>
__global__ __launch_bounds__(256, 2)
void gemm_mma2(const __nv_bfloat16* __restrict__ Ah,
               const __nv_bfloat16* __restrict__ Al,
               const __nv_bfloat16* __restrict__ Bh,
               const __nv_bfloat16* __restrict__ Bl,
               const float* __restrict__ bias,
               float* __restrict__ C,
               __nv_bfloat16* __restrict__ Ch,
               __nv_bfloat16* __restrict__ Cl,
               int N, int scale_n)
{
    extern __shared__ char sm[];
    uint32_t sbase = smem_u32(sm);
    int tid  = threadIdx.x;
    int lane = tid & 31;
    int wid  = tid >> 5;
    int warp_m = wid & 3;
    int warp_n = wid >> 2;
    int m0 = blockIdx.y * 128;
    int n0 = blockIdx.x * 64;

    float acc[2][4][4];
#pragma unroll
    for (int i = 0; i < 2; i++)
#pragma unroll
        for (int j = 0; j < 4; j++)
#pragma unroll
            for (int c = 0; c < 4; c++) acc[i][j][c] = 0.f;

    auto issue = [&](int k0, uint32_t st) {
#pragma unroll
        for (int it = 0; it < 4; it++) {
            int idx = tid + it * 256;
            int row = idx >> 3, cg = idx & 7;
            size_t g = (size_t)(m0 + row) * K_DIM + k0 + cg * 8;
            uint32_t d = sbase + st + (uint32_t)(row * 144 + cg * 16);
            cp_async16(d + G_AH, Ah + g);
            cp_async16(d + G_AL, Al + g);
        }
#pragma unroll
        for (int it = 0; it < 2; it++) {
            int idx = tid + it * 256;
            int row = idx >> 3, cg = idx & 7;
            size_t g = (size_t)(n0 + row) * K_DIM + k0 + cg * 8;
            uint32_t d = sbase + st + (uint32_t)(row * 144 + cg * 16);
            cp_async16(d + G_BH, Bh + g);
            cp_async16(d + G_BL, Bl + g);
        }
    };

    issue(0, 0);
    cp_commit();

    for (int c = 0; c < 16; c++) {
        uint32_t st = (c & 1) ? GST : 0;
        if (c + 1 < 16) {
            issue((c + 1) * 64, ((c + 1) & 1) ? GST : 0);
            cp_commit();
            cp_wait<1>();
        } else {
            cp_wait<0>();
        }
        __syncthreads();

#pragma unroll
        for (int ks = 0; ks < 4; ks++) {
            uint32_t ahi[2][4], alo[2][4];
#pragma unroll
            for (int mf = 0; mf < 2; mf++) {
                int row = warp_m * 32 + mf * 16 + (lane & 15);
                int col = ks * 16 + (lane >> 4) * 8;
                uint32_t ad = sbase + st + (uint32_t)(row * 144 + col * 2);
                ldmatrix_x4(ahi[mf][0], ahi[mf][1], ahi[mf][2], ahi[mf][3], ad + G_AH);
                ldmatrix_x4(alo[mf][0], alo[mf][1], alo[mf][2], alo[mf][3], ad + G_AL);
            }
            uint32_t bhi[4][2], blo[4][2];
#pragma unroll
            for (int np = 0; np < 2; np++) {
                int row = warp_n * 32 + (np * 2 + (lane >> 4)) * 8 + (lane & 7);
                int col = ks * 16 + ((lane >> 3) & 1) * 8;
                uint32_t ad = sbase + st + (uint32_t)(row * 144 + col * 2);
                uint32_t r0, r1, r2, r3;
                ldmatrix_x4(r0, r1, r2, r3, ad + G_BH);
                bhi[np * 2][0] = r0; bhi[np * 2][1] = r1;
                bhi[np * 2 + 1][0] = r2; bhi[np * 2 + 1][1] = r3;
                ldmatrix_x4(r0, r1, r2, r3, ad + G_BL);
                blo[np * 2][0] = r0; blo[np * 2][1] = r1;
                blo[np * 2 + 1][0] = r2; blo[np * 2 + 1][1] = r3;
            }
#pragma unroll
            for (int mf = 0; mf < 2; mf++)
#pragma unroll
                for (int nf = 0; nf < 4; nf++)
                    mma_bf16(acc[mf][nf], ahi[mf], bhi[nf]);
#pragma unroll
            for (int mf = 0; mf < 2; mf++)
#pragma unroll
                for (int nf = 0; nf < 4; nf++)
                    mma_bf16(acc[mf][nf], ahi[mf], blo[nf]);
#pragma unroll
            for (int mf = 0; mf < 2; mf++)
#pragma unroll
                for (int nf = 0; nf < 4; nf++)
                    mma_bf16(acc[mf][nf], alo[mf], bhi[nf]);
        }
        __syncthreads();
    }

#pragma unroll
    for (int mf = 0; mf < 2; mf++) {
#pragma unroll
        for (int nf = 0; nf < 4; nf++) {
            int row = m0 + warp_m * 32 + mf * 16 + (lane >> 2);
            int col = n0 + warp_n * 32 + nf * 8 + (lane & 3) * 2;
            float sc = (col < scale_n) ? 0.125f : 1.0f;
            float b0 = bias[col], b1 = bias[col + 1];
            float d0 = (acc[mf][nf][0] + b0) * sc;
            float d1 = (acc[mf][nf][1] + b1) * sc;
            float d2 = (acc[mf][nf][2] + b0) * sc;
            float d3 = (acc[mf][nf][3] + b1) * sc;
            if (SPLIT_OUT) {
                uint32_t hw, lw;
                split2(d0, d1, hw, lw);
                *(uint32_t*)(Ch + (size_t)row * N + col) = hw;
                *(uint32_t*)(Cl + (size_t)row * N + col) = lw;
                split2(d2, d3, hw, lw);
                *(uint32_t*)(Ch + (size_t)(row + 8) * N + col) = hw;
                *(uint32_t*)(Cl + (size_t)(row + 8) * N + col) = lw;
            } else {
                C[(size_t)row * N + col]           = d0;
                C[(size_t)row * N + col + 1]       = d1;
                C[(size_t)(row + 8) * N + col]     = d2;
                C[(size_t)(row + 8) * N + col + 1] = d3;
            }
        }
    }
}

// ===========================================================================
// KV GEMM: row-gathered A over compacted unmasked keys; early-exit past count.
// ===========================================================================
__global__ __launch_bounds__(256, 2)
void gemm_kv(const __nv_bfloat16* __restrict__ Ah,
             const __nv_bfloat16* __restrict__ Al,
             const __nv_bfloat16* __restrict__ Bh,
             const __nv_bfloat16* __restrict__ Bl,
             const float* __restrict__ bias,
             __nv_bfloat16* __restrict__ Ch,
             __nv_bfloat16* __restrict__ Cl)
{
    extern __shared__ char sm[];
    uint32_t sbase = smem_u32(sm);
    int* s_row = (int*)(sm + G_RM);
    int tid  = threadIdx.x;
    int lane = tid & 31;
    int wid  = tid >> 5;
    int warp_m = wid & 3;
    int warp_n = wid >> 2;
    int m0 = blockIdx.y * 128;
    int n0 = blockIdx.x * 64;
    const int N = 2 * E_DIM;

    int b = (m0 >= T_DIM) ? 1 : 0;
    int j0 = m0 - b * T_DIM;
    int cnt = g_kcount[b];
    if (j0 >= ((cnt + 63) & ~63)) return;

    if (tid < 128)
        s_row[tid] = g_kidx[b * T_DIM + j0 + tid] * 2 + b;
    __syncthreads();

    float acc[2][4][4];
#pragma unroll
    for (int i = 0; i < 2; i++)
#pragma unroll
        for (int j = 0; j < 4; j++)
#pragma unroll
            for (int c = 0; c < 4; c++) acc[i][j][c] = 0.f;

    auto issue = [&](int k0, uint32_t st) {
#pragma unroll
        for (int it = 0; it < 4; it++) {
            int idx = tid + it * 256;
            int row = idx >> 3, cg = idx & 7;
            size_t g = (size_t)s_row[row] * K_DIM + k0 + cg * 8;
            uint32_t d = sbase + st + (uint32_t)(row * 144 + cg * 16);
            cp_async16(d + G_AH, Ah + g);
            cp_async16(d + G_AL, Al + g);
        }
#pragma unroll
        for (int it = 0; it < 2; it++) {
            int idx = tid + it * 256;
            int row = idx >> 3, cg = idx & 7;
            size_t g = (size_t)(n0 + row) * K_DIM + k0 + cg * 8;
            uint32_t d = sbase + st + (uint32_t)(row * 144 + cg * 16);
            cp_async16(d + G_BH, Bh + g);
            cp_async16(d + G_BL, Bl + g);
        }
    };

    issue(0, 0);
    cp_commit();

    for (int c = 0; c < 16; c++) {
        uint32_t st = (c & 1) ? GST : 0;
        if (c + 1 < 16) {
            issue((c + 1) * 64, ((c + 1) & 1) ? GST : 0);
            cp_commit();
            cp_wait<1>();
        } else {
            cp_wait<0>();
        }
        __syncthreads();

#pragma unroll
        for (int ks = 0; ks < 4; ks++) {
            uint32_t ahi[2][4], alo[2][4];
#pragma unroll
            for (int mf = 0; mf < 2; mf++) {
                int row = warp_m * 32 + mf * 16 + (lane & 15);
                int col = ks * 16 + (lane >> 4) * 8;
                uint32_t ad = sbase + st + (uint32_t)(row * 144 + col * 2);
                ldmatrix_x4(ahi[mf][0], ahi[mf][1], ahi[mf][2], ahi[mf][3], ad + G_AH);
                ldmatrix_x4(alo[mf][0], alo[mf][1], alo[mf][2], alo[mf][3], ad + G_AL);
            }
            uint32_t bhi[4][2], blo[4][2];
#pragma unroll
            for (int np = 0; np < 2; np++) {
                int row = warp_n * 32 + (np * 2 + (lane >> 4)) * 8 + (lane & 7);
                int col = ks * 16 + ((lane >> 3) & 1) * 8;
                uint32_t ad = sbase + st + (uint32_t)(row * 144 + col * 2);
                uint32_t r0, r1, r2, r3;
                ldmatrix_x4(r0, r1, r2, r3, ad + G_BH);
                bhi[np * 2][0] = r0; bhi[np * 2][1] = r1;
                bhi[np * 2 + 1][0] = r2; bhi[np * 2 + 1][1] = r3;
                ldmatrix_x4(r0, r1, r2, r3, ad + G_BL);
                blo[np * 2][0] = r0; blo[np * 2][1] = r1;
                blo[np * 2 + 1][0] = r2; blo[np * 2 + 1][1] = r3;
            }
#pragma unroll
            for (int mf = 0; mf < 2; mf++)
#pragma unroll
                for (int nf = 0; nf < 4; nf++)
                    mma_bf16(acc[mf][nf], ahi[mf], bhi[nf]);
#pragma unroll
            for (int mf = 0; mf < 2; mf++)
#pragma unroll
                for (int nf = 0; nf < 4; nf++)
                    mma_bf16(acc[mf][nf], ahi[mf], blo[nf]);
#pragma unroll
            for (int mf = 0; mf < 2; mf++)
#pragma unroll
                for (int nf = 0; nf < 4; nf++)
                    mma_bf16(acc[mf][nf], alo[mf], bhi[nf]);
        }
        __syncthreads();
    }

#pragma unroll
    for (int mf = 0; mf < 2; mf++) {
#pragma unroll
        for (int nf = 0; nf < 4; nf++) {
            int row = m0 + warp_m * 32 + mf * 16 + (lane >> 2);
            int col = n0 + warp_n * 32 + nf * 8 + (lane & 3) * 2;
            float b0 = bias[col], b1 = bias[col + 1];
            float d0 = acc[mf][nf][0] + b0;
            float d1 = acc[mf][nf][1] + b1;
            float d2 = acc[mf][nf][2] + b0;
            float d3 = acc[mf][nf][3] + b1;
            uint32_t hw, lw;
            split2(d0, d1, hw, lw);
            *(uint32_t*)(Ch + (size_t)row * N + col) = hw;
            *(uint32_t*)(Cl + (size_t)row * N + col) = lw;
            split2(d2, d3, hw, lw);
            *(uint32_t*)(Ch + (size_t)(row + 8) * N + col) = hw;
            *(uint32_t*)(Cl + (size_t)(row + 8) * N + col) = lw;
        }
    }
}

// ===========================================================================
// Flash attention v7: key-compacted, contiguous K/V, Q FRAGMENTS HOISTED
// into registers (loaded once; halves LDSM in the steady-state loop).
// ===========================================================================
#define F_QH   0
#define F_QL   18432
#define F_ST0  36864
#define F_ST1  73728
#define F_KH   0
#define F_KL   9216
#define F_VH   18432
#define F_VL   27648
#define F_MSK0 110592
#define F_MSK1 110848
#define F_TOTAL 111104

__global__ __launch_bounds__(128, 2)
void flash_mma7(const __nv_bfloat16* __restrict__ q_hi,
                const __nv_bfloat16* __restrict__ q_lo,
                const __nv_bfloat16* __restrict__ kv_hi,
                const __nv_bfloat16* __restrict__ kv_lo,
                __nv_bfloat16* __restrict__ attn_hi,
                __nv_bfloat16* __restrict__ attn_lo)
{
    extern __shared__ char sm[];
    uint32_t sbase = smem_u32(sm);
    float* msk0 = (float*)(sm + F_MSK0);
    float* msk1 = (float*)(sm + F_MSK1);
    int tid = threadIdx.x;
    int lane = tid & 31;
    int w = tid >> 5;
    int b = blockIdx.z;
    int h = blockIdx.y;
    int q0 = blockIdx.x * 128;
    int qbase = w * 32;

    int cnt = g_kcount[b];
    int ntiles = (cnt + 63) >> 6;

    // ---- stage Q tile (group 0) ----
#pragma unroll
    for (int it = 0; it < 8; it++) {
        int idx = tid + it * 128;
        int row = idx >> 3, cg = idx & 7;
        size_t g = (size_t)((q0 + row) * 2 + b) * E_DIM + h * 64 + cg * 8;
        uint32_t d = sbase + (uint32_t)(row * 144 + cg * 16);
        cp_async16(d + F_QH, q_hi + g);
        cp_async16(d + F_QL, q_lo + g);
    }
    cp_commit();

    auto issue_kv = [&](int s0, uint32_t st) {
#pragma unroll
        for (int it = 0; it < 4; it++) {
            int idx = tid + it * 128;
            int row = idx >> 3, cg = idx & 7;
            size_t g = (size_t)(b * T_DIM + s0 + row) * (2 * E_DIM) + h * 64 + cg * 8;
            uint32_t d = sbase + st + (uint32_t)(row * 144 + cg * 16);
            cp_async16(d + F_KH, kv_hi + g);
            cp_async16(d + F_KL, kv_lo + g);
            cp_async16(d + F_VH, kv_hi + g + E_DIM);
            cp_async16(d + F_VL, kv_lo + g + E_DIM);
        }
    };

    // ---- stage KV tile 0 (group 1) ----
    issue_kv(0, F_ST0);
    if (tid < 64)
        msk0[tid] = g_kmask[b * T_DIM + tid];
    cp_commit();

    // ---- hoist Q fragments to registers (Q smem never reused) ----
    cp_wait<1>();            // group 0 (Q) complete; kv0 may be in flight
    __syncthreads();
    uint32_t qfh[2][4][4], qfl[2][4][4];
#pragma unroll
    for (int kf = 0; kf < 4; kf++)
#pragma unroll
        for (int mf = 0; mf < 2; mf++) {
            int row = qbase + mf * 16 + (lane & 15);
            int col = kf * 16 + (lane >> 4) * 8;
            uint32_t ad = sbase + (uint32_t)(row * 144 + col * 2);
            ldmatrix_x4(qfh[mf][kf][0], qfh[mf][kf][1],
                        qfh[mf][kf][2], qfh[mf][kf][3], ad + F_QH);
            ldmatrix_x4(qfl[mf][kf][0], qfl[mf][kf][1],
                        qfl[mf][kf][2], qfl[mf][kf][3], ad + F_QL);
        }

    float l[2][2];
    l[0][0] = l[0][1] = l[1][0] = l[1][1] = 0.f;
    float o[2][8][4];
#pragma unroll
    for (int mf = 0; mf < 2; mf++)
#pragma unroll
        for (int nf = 0; nf < 8; nf++)
#pragma unroll
            for (int c = 0; c < 4; c++) o[mf][nf][c] = 0.f;

    for (int c = 0; c < ntiles; c++) {
        uint32_t st = (c & 1) ? F_ST1 : F_ST0;
        float* mk = (c & 1) ? msk1 : msk0;
        if (c + 1 < ntiles) {
            issue_kv((c + 1) * 64, ((c + 1) & 1) ? F_ST1 : F_ST0);
            float* mkn = ((c + 1) & 1) ? msk1 : msk0;
            if (tid < 64)
                mkn[tid] = g_kmask[b * T_DIM + (c + 1) * 64 + tid];
            cp_commit();
            cp_wait<1>();
        } else {
            cp_wait<0>();
        }
        __syncthreads();

        // ---- S = Q K^T, pass-major, Q from registers ----
        float acc[2][8][4];
#pragma unroll
        for (int mf = 0; mf < 2; mf++)
#pragma unroll
            for (int nf = 0; nf < 8; nf++)
#pragma unroll
                for (int cc = 0; cc < 4; cc++) acc[mf][nf][cc] = 0.f;

#pragma unroll
        for (int kf = 0; kf < 4; kf++) {
            uint32_t khi[4][4], klo[4][4];
#pragma unroll
            for (int np = 0; np < 4; np++) {
                int row = (np * 2 + (lane >> 4)) * 8 + (lane & 7);
                int col = kf * 16 + ((lane >> 3) & 1) * 8;
                uint32_t ad = sbase + st + (uint32_t)(row * 144 + col * 2);
                ldmatrix_x4(khi[np][0], khi[np][1], khi[np][2], khi[np][3], ad + F_KH);
                ldmatrix_x4(klo[np][0], klo[np][1], klo[np][2], klo[np][3], ad + F_KL);
            }
#pragma unroll
            for (int mf = 0; mf < 2; mf++)
#pragma unroll
                for (int np = 0; np < 4; np++) {
                    mma_bf16(acc[mf][np * 2],     qfh[mf][kf], khi[np]);
                    mma_bf16(acc[mf][np * 2 + 1], qfh[mf][kf], khi[np] + 2);
                }
#pragma unroll
            for (int mf = 0; mf < 2; mf++)
#pragma unroll
                for (int np = 0; np < 4; np++) {
                    mma_bf16(acc[mf][np * 2],     qfh[mf][kf], klo[np]);
                    mma_bf16(acc[mf][np * 2 + 1], qfh[mf][kf], klo[np] + 2);
                }
#pragma unroll
            for (int mf = 0; mf < 2; mf++)
#pragma unroll
                for (int np = 0; np < 4; np++) {
                    mma_bf16(acc[mf][np * 2],     qfl[mf][kf], khi[np]);
                    mma_bf16(acc[mf][np * 2 + 1], qfl[mf][kf], khi[np] + 2);
                }
        }

        // ---- pad-mask + exp (fixed reference m = 0) ----
#pragma unroll
        for (int mf = 0; mf < 2; mf++) {
            float rs1 = 0.f, rs2 = 0.f;
#pragma unroll
            for (int nf = 0; nf < 8; nf++) {
                float2 mv = *(float2*)&mk[nf * 8 + (lane & 3) * 2];
                float p0 = __expf(acc[mf][nf][0] + mv.x);
                float p1 = __expf(acc[mf][nf][1] + mv.y);
                float p2 = __expf(acc[mf][nf][2] + mv.x);
                float p3 = __expf(acc[mf][nf][3] + mv.y);
                acc[mf][nf][0] = p0; acc[mf][nf][1] = p1;
                acc[mf][nf][2] = p2; acc[mf][nf][3] = p3;
                rs1 += p0 + p1;
                rs2 += p2 + p3;
            }
            rs1 += __shfl_xor_sync(0xffffffffu, rs1, 1);
            rs1 += __shfl_xor_sync(0xffffffffu, rs1, 2);
            rs2 += __shfl_xor_sync(0xffffffffu, rs2, 1);
            rs2 += __shfl_xor_sync(0xffffffffu, rs2, 2);
            l[mf][0] += rs1;
            l[mf][1] += rs2;
        }

        // ---- O += P V, pass-major ----
#pragma unroll
        for (int kf = 0; kf < 4; kf++) {
            uint32_t phi[2][4], plo[2][4];
#pragma unroll
            for (int mf = 0; mf < 2; mf++) {
                split2(acc[mf][2 * kf][0],     acc[mf][2 * kf][1],     phi[mf][0], plo[mf][0]);
                split2(acc[mf][2 * kf][2],     acc[mf][2 * kf][3],     phi[mf][1], plo[mf][1]);
                split2(acc[mf][2 * kf + 1][0], acc[mf][2 * kf + 1][1], phi[mf][2], plo[mf][2]);
                split2(acc[mf][2 * kf + 1][2], acc[mf][2 * kf + 1][3], phi[mf][3], plo[mf][3]);
            }
            uint32_t vhi[4][4], vlo[4][4];
#pragma unroll
            for (int np = 0; np < 4; np++) {
                int row = kf * 16 + (lane & 15);
                int col = (np * 2 + (lane >> 4)) * 8;
                uint32_t ad = sbase + st + (uint32_t)(row * 144 + col * 2);
                ldmatrix_x4_trans(vhi[np][0], vhi[np][1], vhi[np][2], vhi[np][3], ad + F_VH);
                ldmatrix_x4_trans(vlo[np][0], vlo[np][1], vlo[np][2], vlo[np][3], ad + F_VL);
            }
#pragma unroll
            for (int mf = 0; mf < 2; mf++)
#pragma unroll
                for (int np = 0; np < 4; np++) {
                    mma_bf16(o[mf][np * 2],     phi[mf], vhi[np]);
                    mma_bf16(o[mf][np * 2 + 1], phi[mf], vhi[np] + 2);
                }
#pragma unroll
            for (int mf = 0; mf < 2; mf++)
#pragma unroll
                for (int np = 0; np < 4; np++) {
                    mma_bf16(o[mf][np * 2],     phi[mf], vlo[np]);
                    mma_bf16(o[mf][np * 2 + 1], phi[mf], vlo[np] + 2);
                }
#pragma unroll
            for (int mf = 0; mf < 2; mf++)
#pragma unroll
                for (int np = 0; np < 4; np++) {
                    mma_bf16(o[mf][np * 2],     plo[mf], vhi[np]);
                    mma_bf16(o[mf][np * 2 + 1], plo[mf], vhi[np] + 2);
                }
        }
        __syncthreads();
    }

    // ---- epilogue ----
#pragma unroll
    for (int mf = 0; mf < 2; mf++) {
        float inv1 = 1.f / l[mf][0];
        float inv2 = 1.f / l[mf][1];
        int t1 = q0 + qbase + mf * 16 + (lane >> 2);
        int t2 = t1 + 8;
#pragma unroll
        for (int nf = 0; nf < 8; nf++) {
            int d = h * 64 + nf * 8 + (lane & 3) * 2;
            size_t r1 = (size_t)(t1 * 2 + b) * E_DIM + d;
            size_t r2 = (size_t)(t2 * 2 + b) * E_DIM + d;
            uint32_t hw, lw;
            split2(o[mf][nf][0] * inv1, o[mf][nf][1] * inv1, hw, lw);
            *(uint32_t*)(attn_hi + r1) = hw;
            *(uint32_t*)(attn_lo + r1) = lw;
            split2(o[mf][nf][2] * inv2, o[mf][nf][3] * inv2, hw, lw);
            *(uint32_t*)(attn_hi + r2) = hw;
            *(uint32_t*)(attn_lo + r2) = lw;
        }
    }
}

// ===========================================================================
extern "C" void kernel_launch(void* const* d_in, const int* in_sizes, int n_in,
                              void* d_out, int out_size)
{
    const float* x      = (const float*)d_in[0];
    const float* w_in   = (const float*)d_in[1];
    const float* b_in   = (const float*)d_in[2];
    const float* w_out  = (const float*)d_in[3];
    const float* b_out  = (const float*)d_in[4];
    const void*  mask   = d_in[5];
    float* out = (float*)d_out;

    __nv_bfloat16 *x_hi, *x_lo, *win_hi, *win_lo, *wout_hi, *wout_lo;
    __nv_bfloat16 *q_hi, *q_lo, *kv_hi, *kv_lo, *attn_hi, *attn_lo;
    cudaGetSymbolAddress((void**)&x_hi, g_x_hi);
    cudaGetSymbolAddress((void**)&x_lo, g_x_lo);
    cudaGetSymbolAddress((void**)&win_hi, g_win_hi);
    cudaGetSymbolAddress((void**)&win_lo, g_win_lo);
    cudaGetSymbolAddress((void**)&wout_hi, g_wout_hi);
    cudaGetSymbolAddress((void**)&wout_lo, g_wout_lo);
    cudaGetSymbolAddress((void**)&q_hi, g_q_hi);
    cudaGetSymbolAddress((void**)&q_lo, g_q_lo);
    cudaGetSymbolAddress((void**)&kv_hi, g_kv_hi);
    cudaGetSymbolAddress((void**)&kv_lo, g_kv_lo);
    cudaGetSymbolAddress((void**)&attn_hi, g_attn_hi);
    cudaGetSymbolAddress((void**)&attn_lo, g_attn_lo);

    cudaFuncSetAttribute(gemm_mma2<true>,
                         cudaFuncAttributeMaxDynamicSharedMemorySize, G_TOTAL);
    cudaFuncSetAttribute(gemm_mma2<false>,
                         cudaFuncAttributeMaxDynamicSharedMemorySize, G_TOTAL);
    cudaFuncSetAttribute(gemm_kv,
                         cudaFuncAttributeMaxDynamicSharedMemorySize, G_TOTAL_KV);
    cudaFuncSetAttribute(flash_mma7,
                         cudaFuncAttributeMaxDynamicSharedMemorySize, F_TOTAL);

    // 0) mask prep (single kernel) + pre-split inputs
    mask_prep_kernel<<<1, 256>>>(mask);
    presplit_kernel<<<(MROWS * E_DIM / 4 + 255) / 256, 256>>>(x, x_hi, x_lo,
                                                              MROWS * E_DIM / 4);
    presplit_kernel<<<(3 * E_DIM * E_DIM / 4 + 255) / 256, 256>>>(
        w_in, win_hi, win_lo, 3 * E_DIM * E_DIM / 4);
    presplit_kernel<<<(E_DIM * E_DIM / 4 + 255) / 256, 256>>>(
        w_out, wout_hi, wout_lo, E_DIM * E_DIM / 4);

    // 1a) q = x @ Wq^T + bq, scaled 0.125 -> split bf16 (full rows)
    {
        dim3 grid(E_DIM / 64, MROWS / 128);
        gemm_mma2<true><<<grid, 256, G_TOTAL>>>(x_hi, x_lo, win_hi, win_lo,
                                                b_in, nullptr,
                                                q_hi, q_lo, E_DIM, E_DIM);
    }
    // 1b) k|v = gathered x @ Wkv^T + bkv -> compacted split bf16
    {
        dim3 grid((2 * E_DIM) / 64, MROWS / 128);
        gemm_kv<<<grid, 256, G_TOTAL_KV>>>(x_hi, x_lo,
                                           win_hi + (size_t)E_DIM * K_DIM,
                                           win_lo + (size_t)E_DIM * K_DIM,
                                           b_in + E_DIM,
                                           kv_hi, kv_lo);
    }

    // 2) flash attention (compacted, Q hoisted) -> split bf16 attn
    {
        dim3 grid(T_DIM / 128, H_DIM, B_DIM);
        flash_mma7<<<grid, 128, F_TOTAL>>>(q_hi, q_lo, kv_hi, kv_lo,
                                           attn_hi, attn_lo);
    }

    // 3) out = attn @ W_out^T + b_out   [4096 x 1024] fp32
    {
        dim3 grid(E_DIM / 64, MROWS / 128);
        gemm_mma2<false><<<grid, 256, G_TOTAL>>>(attn_hi, attn_lo,
                                                 wout_hi, wout_lo,
                                                 b_out, out,
                                                 nullptr, nullptr, E_DIM, 0);
    }
}

// round 12
// speedup vs baseline: 1.0465x; 1.0465x over previous
#include <cuda_runtime.h>
#include <cuda_bf16.h>
#include <cstdint>
#include <cstddef>

#define T_DIM 2048
#define B_DIM 2
#define E_DIM 1024
#define H_DIM 16
#define MROWS (T_DIM * B_DIM)      // 4096
#define K_DIM 1024
#define NEG_INF_F (-1e24f)

// ---------------------------------------------------------------------------
// Scratch (no cudaMalloc allowed)
// ---------------------------------------------------------------------------
__device__ __nv_bfloat16 g_x_hi[(size_t)MROWS * E_DIM];
__device__ __nv_bfloat16 g_x_lo[(size_t)MROWS * E_DIM];
__device__ __nv_bfloat16 g_win_hi[(size_t)3 * E_DIM * E_DIM];
__device__ __nv_bfloat16 g_win_lo[(size_t)3 * E_DIM * E_DIM];
__device__ __nv_bfloat16 g_wout_hi[(size_t)E_DIM * E_DIM];
__device__ __nv_bfloat16 g_wout_lo[(size_t)E_DIM * E_DIM];
__device__ __nv_bfloat16 g_q_hi[(size_t)MROWS * E_DIM];
__device__ __nv_bfloat16 g_q_lo[(size_t)MROWS * E_DIM];
// compacted K|V: row = b*2048 + compact_j, cols [0,1024)=K, [1024,2048)=V
__device__ __nv_bfloat16 g_kv_hi[(size_t)MROWS * 2 * E_DIM];
__device__ __nv_bfloat16 g_kv_lo[(size_t)MROWS * 2 * E_DIM];
__device__ __nv_bfloat16 g_attn_hi[(size_t)MROWS * E_DIM];
__device__ __nv_bfloat16 g_attn_lo[(size_t)MROWS * E_DIM];
__device__ unsigned char g_mask[MROWS];
__device__ int   g_kidx[B_DIM * T_DIM];
__device__ int   g_kcount[B_DIM];
__device__ float g_kmask[B_DIM * T_DIM];

// ===========================================================================
// PTX helpers
// ===========================================================================
__device__ __forceinline__ uint32_t smem_u32(const void* p) {
    uint32_t a;
    asm("{ .reg .u64 t; cvta.to.shared.u64 t, %1; cvt.u32.u64 %0, t; }"
        : "=r"(a) : "l"(p));
    return a;
}
__device__ __forceinline__ void ldmatrix_x4(uint32_t& r0, uint32_t& r1,
                                            uint32_t& r2, uint32_t& r3,
                                            uint32_t addr) {
    asm volatile("ldmatrix.sync.aligned.m8n8.x4.shared.b16 {%0,%1,%2,%3}, [%4];"
                 : "=r"(r0), "=r"(r1), "=r"(r2), "=r"(r3) : "r"(addr));
}
__device__ __forceinline__ void ldmatrix_x4_trans(uint32_t& r0, uint32_t& r1,
                                                  uint32_t& r2, uint32_t& r3,
                                                  uint32_t addr) {
    asm volatile("ldmatrix.sync.aligned.m8n8.x4.trans.shared.b16 {%0,%1,%2,%3}, [%4];"
                 : "=r"(r0), "=r"(r1), "=r"(r2), "=r"(r3) : "r"(addr));
}
__device__ __forceinline__ void mma_bf16(float* d, const uint32_t* a,
                                         const uint32_t* b) {
    asm("mma.sync.aligned.m16n8k16.row.col.f32.bf16.bf16.f32 "
        "{%0,%1,%2,%3}, {%4,%5,%6,%7}, {%8,%9}, {%0,%1,%2,%3};"
        : "+f"(d[0]), "+f"(d[1]), "+f"(d[2]), "+f"(d[3])
        : "r"(a[0]), "r"(a[1]), "r"(a[2]), "r"(a[3]), "r"(b[0]), "r"(b[1]));
}
__device__ __forceinline__ void cp_async16(uint32_t dst, const void* src) {
    asm volatile("cp.async.cg.shared.global [%0], [%1], 16;" :: "r"(dst), "l"(src));
}
__device__ __forceinline__ void cp_commit() {
    asm volatile("cp.async.commit_group;" ::: "memory");
}
template<int N> __device__ __forceinline__ void cp_wait() {
    asm volatile("cp.async.wait_group %0;" :: "n"(N) : "memory");
}

__device__ __forceinline__ void split2(float x, float y,
                                       uint32_t& hi, uint32_t& lo) {
    __nv_bfloat16 hx = __float2bfloat16(x);
    __nv_bfloat16 hy = __float2bfloat16(y);
    __nv_bfloat16 lx = __float2bfloat16(x - __bfloat162float(hx));
    __nv_bfloat16 ly = __float2bfloat16(y - __bfloat162float(hy));
    __nv_bfloat162 hp = __halves2bfloat162(hx, hy);
    __nv_bfloat162 lp = __halves2bfloat162(lx, ly);
    hi = *(uint32_t*)&hp;
    lo = *(uint32_t*)&lp;
}

// ===========================================================================
// Mask prep (single kernel, single block): detect dtype, expand, compact.
// ===========================================================================
__global__ void mask_prep_kernel(const void* __restrict__ mv)
{
    const unsigned char* m8 = (const unsigned char*)mv;
    __shared__ int s_nz, s_f32;
    int tid = threadIdx.x;
    if (tid == 0) { s_nz = 0; s_f32 = 0; }
    __syncthreads();
    int nz = 0, f32 = 0;
    for (int i = tid; i < MROWS; i += 256) {
        unsigned char v = m8[i];
        if ((i & 3) != 0 && v != 0) nz = 1;
        if ((i & 3) == 3 && v == 0x3F) f32 = 1;
    }
    if (nz)  atomicOr(&s_nz, 1);
    if (f32) atomicOr(&s_f32, 1);
    __syncthreads();
    int mode = s_f32 ? 2 : (s_nz ? 0 : 1);
    for (int i = tid; i < MROWS; i += 256) {
        unsigned char r;
        if (mode == 0)      r = m8[i] != 0;
        else if (mode == 1) r = ((const int*)mv)[i] != 0;
        else                r = ((const float*)mv)[i] != 0.0f;
        g_mask[i] = r;
    }
    __syncthreads();
    if (tid < 64) {
        int b = tid >> 5, lane = tid & 31;
        int base = 0;
        for (int j0 = 0; j0 < T_DIM; j0 += 32) {
            int t = j0 + lane;
            int keep = g_mask[t * B_DIM + b] ? 0 : 1;
            unsigned bal = __ballot_sync(0xffffffffu, keep);
            int pre = __popc(bal & ((1u << lane) - 1));
            if (keep) g_kidx[b * T_DIM + base + pre] = t;
            base += __popc(bal);
        }
        if (lane == 0) g_kcount[b] = base;
        for (int j = base + lane; j < T_DIM; j += 32)
            g_kidx[b * T_DIM + j] = 0;
        for (int j = lane; j < T_DIM; j += 32)
            g_kmask[b * T_DIM + j] = (j < base) ? 0.f : NEG_INF_F;
    }
}

// ===========================================================================
// Pre-split fp32 -> bf16 hi/lo
// ===========================================================================
__global__ void presplit_kernel(const float* __restrict__ src,
                                __nv_bfloat16* __restrict__ hi,
                                __nv_bfloat16* __restrict__ lo, int n4)
{
    int i = blockIdx.x * 256 + threadIdx.x;
    if (i >= n4) return;
    float4 v = ((const float4*)src)[i];
    uint32_t h0, l0, h1, l1;
    split2(v.x, v.y, h0, l0);
    split2(v.z, v.w, h1, l1);
    uint2 hh, ll;
    hh.x = h0; hh.y = h1;
    ll.x = l0; ll.y = l1;
    ((uint2*)hi)[i] = hh;
    ((uint2*)lo)[i] = ll;
}

// ===========================================================================
// Shared GEMM smem layout
// ===========================================================================
#define GST   55296
#define G_AH  0
#define G_AL  18432
#define G_BH  36864
#define G_BL  46080
#define G_TOTAL (2 * GST)
#define G_RM  G_TOTAL
#define G_TOTAL_RM (G_TOTAL + 512)

// ===========================================================================
// Dense 2-stage split-bf16 HMMA GEMM (used for out projection)
// ===========================================================================
__global__ __launch_bounds__(256, 2)
void gemm_dense(const __nv_bfloat16* __restrict__ Ah,
                const __nv_bfloat16* __restrict__ Al,
                const __nv_bfloat16* __restrict__ Bh,
                const __nv_bfloat16* __restrict__ Bl,
                const float* __restrict__ bias,
                float* __restrict__ C, int N)
{
    extern __shared__ char sm[];
    uint32_t sbase = smem_u32(sm);
    int tid  = threadIdx.x;
    int lane = tid & 31;
    int wid  = tid >> 5;
    int warp_m = wid & 3;
    int warp_n = wid >> 2;
    int m0 = blockIdx.y * 128;
    int n0 = blockIdx.x * 64;

    float acc[2][4][4];
#pragma unroll
    for (int i = 0; i < 2; i++)
#pragma unroll
        for (int j = 0; j < 4; j++)
#pragma unroll
            for (int c = 0; c < 4; c++) acc[i][j][c] = 0.f;

    auto issue = [&](int k0, uint32_t st) {
#pragma unroll
        for (int it = 0; it < 4; it++) {
            int idx = tid + it * 256;
            int row = idx >> 3, cg = idx & 7;
            size_t g = (size_t)(m0 + row) * K_DIM + k0 + cg * 8;
            uint32_t d = sbase + st + (uint32_t)(row * 144 + cg * 16);
            cp_async16(d + G_AH, Ah + g);
            cp_async16(d + G_AL, Al + g);
        }
#pragma unroll
        for (int it = 0; it < 2; it++) {
            int idx = tid + it * 256;
            int row = idx >> 3, cg = idx & 7;
            size_t g = (size_t)(n0 + row) * K_DIM + k0 + cg * 8;
            uint32_t d = sbase + st + (uint32_t)(row * 144 + cg * 16);
            cp_async16(d + G_BH, Bh + g);
            cp_async16(d + G_BL, Bl + g);
        }
    };

    issue(0, 0);
    cp_commit();

    for (int c = 0; c < 16; c++) {
        uint32_t st = (c & 1) ? GST : 0;
        if (c + 1 < 16) {
            issue((c + 1) * 64, ((c + 1) & 1) ? GST : 0);
            cp_commit();
            cp_wait<1>();
        } else {
            cp_wait<0>();
        }
        __syncthreads();

#pragma unroll
        for (int ks = 0; ks < 4; ks++) {
            uint32_t ahi[2][4], alo[2][4];
#pragma unroll
            for (int mf = 0; mf < 2; mf++) {
                int row = warp_m * 32 + mf * 16 + (lane & 15);
                int col = ks * 16 + (lane >> 4) * 8;
                uint32_t ad = sbase + st + (uint32_t)(row * 144 + col * 2);
                ldmatrix_x4(ahi[mf][0], ahi[mf][1], ahi[mf][2], ahi[mf][3], ad + G_AH);
                ldmatrix_x4(alo[mf][0], alo[mf][1], alo[mf][2], alo[mf][3], ad + G_AL);
            }
            uint32_t bhi[4][2], blo[4][2];
#pragma unroll
            for (int np = 0; np < 2; np++) {
                int row = warp_n * 32 + (np * 2 + (lane >> 4)) * 8 + (lane & 7);
                int col = ks * 16 + ((lane >> 3) & 1) * 8;
                uint32_t ad = sbase + st + (uint32_t)(row * 144 + col * 2);
                uint32_t r0, r1, r2, r3;
                ldmatrix_x4(r0, r1, r2, r3, ad + G_BH);
                bhi[np * 2][0] = r0; bhi[np * 2][1] = r1;
                bhi[np * 2 + 1][0] = r2; bhi[np * 2 + 1][1] = r3;
                ldmatrix_x4(r0, r1, r2, r3, ad + G_BL);
                blo[np * 2][0] = r0; blo[np * 2][1] = r1;
                blo[np * 2 + 1][0] = r2; blo[np * 2 + 1][1] = r3;
            }
#pragma unroll
            for (int mf = 0; mf < 2; mf++)
#pragma unroll
                for (int nf = 0; nf < 4; nf++)
                    mma_bf16(acc[mf][nf], ahi[mf], bhi[nf]);
#pragma unroll
            for (int mf = 0; mf < 2; mf++)
#pragma unroll
                for (int nf = 0; nf < 4; nf++)
                    mma_bf16(acc[mf][nf], ahi[mf], blo[nf]);
#pragma unroll
            for (int mf = 0; mf < 2; mf++)
#pragma unroll
                for (int nf = 0; nf < 4; nf++)
                    mma_bf16(acc[mf][nf], alo[mf], bhi[nf]);
        }
        __syncthreads();
    }

#pragma unroll
    for (int mf = 0; mf < 2; mf++) {
#pragma unroll
        for (int nf = 0; nf < 4; nf++) {
            int row = m0 + warp_m * 32 + mf * 16 + (lane >> 2);
            int col = n0 + warp_n * 32 + nf * 8 + (lane & 3) * 2;
            float b0 = bias[col], b1 = bias[col + 1];
            C[(size_t)row * N + col]           = acc[mf][nf][0] + b0;
            C[(size_t)row * N + col + 1]       = acc[mf][nf][1] + b1;
            C[(size_t)(row + 8) * N + col]     = acc[mf][nf][2] + b0;
            C[(size_t)(row + 8) * N + col + 1] = acc[mf][nf][3] + b1;
        }
    }
}

// ===========================================================================
// Fused q + kv projection GEMM. blockIdx.x < 16 -> q path (dense rows,
// scaled 0.125, out g_q). Else kv path (gathered compacted rows, out g_kv,
// early exit past count). A rows resolved through smem row map for both.
// ===========================================================================
__global__ __launch_bounds__(256, 2)
void gemm_qkv(const __nv_bfloat16* __restrict__ Ah,
              const __nv_bfloat16* __restrict__ Al,
              const __nv_bfloat16* __restrict__ Wh,   // full w_in split [3072,1024]
              const __nv_bfloat16* __restrict__ Wl,
              const float* __restrict__ bias,         // full b_in [3072]
              __nv_bfloat16* __restrict__ Qh,
              __nv_bfloat16* __restrict__ Ql,
              __nv_bfloat16* __restrict__ KVh,
              __nv_bfloat16* __restrict__ KVl)
{
    extern __shared__ char sm[];
    uint32_t sbase = smem_u32(sm);
    int* s_row = (int*)(sm + G_RM);
    int tid  = threadIdx.x;
    int lane = tid & 31;
    int wid  = tid >> 5;
    int warp_m = wid & 3;
    int warp_n = wid >> 2;
    int m0 = blockIdx.y * 128;
    bool is_q = blockIdx.x < 16;
    int n0 = is_q ? blockIdx.x * 64 : (blockIdx.x - 16) * 64;   // within output
    int wrow0 = is_q ? n0 : (E_DIM + n0);                        // w_in row base

    int b = 0, j0 = 0;
    if (!is_q) {
        b = (m0 >= T_DIM) ? 1 : 0;
        j0 = m0 - b * T_DIM;
        int cnt = g_kcount[b];
        if (j0 >= ((cnt + 63) & ~63)) return;
    }

    if (tid < 128)
        s_row[tid] = is_q ? (m0 + tid) : (g_kidx[b * T_DIM + j0 + tid] * 2 + b);
    __syncthreads();

    float acc[2][4][4];
#pragma unroll
    for (int i = 0; i < 2; i++)
#pragma unroll
        for (int j = 0; j < 4; j++)
#pragma unroll
            for (int c = 0; c < 4; c++) acc[i][j][c] = 0.f;

    auto issue = [&](int k0, uint32_t st) {
#pragma unroll
        for (int it = 0; it < 4; it++) {
            int idx = tid + it * 256;
            int row = idx >> 3, cg = idx & 7;
            size_t g = (size_t)s_row[row] * K_DIM + k0 + cg * 8;
            uint32_t d = sbase + st + (uint32_t)(row * 144 + cg * 16);
            cp_async16(d + G_AH, Ah + g);
            cp_async16(d + G_AL, Al + g);
        }
#pragma unroll
        for (int it = 0; it < 2; it++) {
            int idx = tid + it * 256;
            int row = idx >> 3, cg = idx & 7;
            size_t g = (size_t)(wrow0 + row) * K_DIM + k0 + cg * 8;
            uint32_t d = sbase + st + (uint32_t)(row * 144 + cg * 16);
            cp_async16(d + G_BH, Wh + g);
            cp_async16(d + G_BL, Wl + g);
        }
    };

    issue(0, 0);
    cp_commit();

    for (int c = 0; c < 16; c++) {
        uint32_t st = (c & 1) ? GST : 0;
        if (c + 1 < 16) {
            issue((c + 1) * 64, ((c + 1) & 1) ? GST : 0);
            cp_commit();
            cp_wait<1>();
        } else {
            cp_wait<0>();
        }
        __syncthreads();

#pragma unroll
        for (int ks = 0; ks < 4; ks++) {
            uint32_t ahi[2][4], alo[2][4];
#pragma unroll
            for (int mf = 0; mf < 2; mf++) {
                int row = warp_m * 32 + mf * 16 + (lane & 15);
                int col = ks * 16 + (lane >> 4) * 8;
                uint32_t ad = sbase + st + (uint32_t)(row * 144 + col * 2);
                ldmatrix_x4(ahi[mf][0], ahi[mf][1], ahi[mf][2], ahi[mf][3], ad + G_AH);
                ldmatrix_x4(alo[mf][0], alo[mf][1], alo[mf][2], alo[mf][3], ad + G_AL);
            }
            uint32_t bhi[4][2], blo[4][2];
#pragma unroll
            for (int np = 0; np < 2; np++) {
                int row = warp_n * 32 + (np * 2 + (lane >> 4)) * 8 + (lane & 7);
                int col = ks * 16 + ((lane >> 3) & 1) * 8;
                uint32_t ad = sbase + st + (uint32_t)(row * 144 + col * 2);
                uint32_t r0, r1, r2, r3;
                ldmatrix_x4(r0, r1, r2, r3, ad + G_BH);
                bhi[np * 2][0] = r0; bhi[np * 2][1] = r1;
                bhi[np * 2 + 1][0] = r2; bhi[np * 2 + 1][1] = r3;
                ldmatrix_x4(r0, r1, r2, r3, ad + G_BL);
                blo[np * 2][0] = r0; blo[np * 2][1] = r1;
                blo[np * 2 + 1][0] = r2; blo[np * 2 + 1][1] = r3;
            }
#pragma unroll
            for (int mf = 0; mf < 2; mf++)
#pragma unroll
                for (int nf = 0; nf < 4; nf++)
                    mma_bf16(acc[mf][nf], ahi[mf], bhi[nf]);
#pragma unroll
            for (int mf = 0; mf < 2; mf++)
#pragma unroll
                for (int nf = 0; nf < 4; nf++)
                    mma_bf16(acc[mf][nf], ahi[mf], blo[nf]);
#pragma unroll
            for (int mf = 0; mf < 2; mf++)
#pragma unroll
                for (int nf = 0; nf < 4; nf++)
                    mma_bf16(acc[mf][nf], alo[mf], bhi[nf]);
        }
        __syncthreads();
    }

    int N = is_q ? E_DIM : 2 * E_DIM;
    __nv_bfloat16* Ch = is_q ? Qh : KVh;
    __nv_bfloat16* Cl = is_q ? Ql : KVl;
    float sc = is_q ? 0.125f : 1.0f;
#pragma unroll
    for (int mf = 0; mf < 2; mf++) {
#pragma unroll
        for (int nf = 0; nf < 4; nf++) {
            int row = m0 + warp_m * 32 + mf * 16 + (lane >> 2);
            int col = n0 + warp_n * 32 + nf * 8 + (lane & 3) * 2;
            int bcol = wrow0 + warp_n * 32 + nf * 8 + (lane & 3) * 2;
            float b0 = bias[bcol], b1 = bias[bcol + 1];
            float d0 = (acc[mf][nf][0] + b0) * sc;
            float d1 = (acc[mf][nf][1] + b1) * sc;
            float d2 = (acc[mf][nf][2] + b0) * sc;
            float d3 = (acc[mf][nf][3] + b1) * sc;
            uint32_t hw, lw;
            split2(d0, d1, hw, lw);
            *(uint32_t*)(Ch + (size_t)row * N + col) = hw;
            *(uint32_t*)(Cl + (size_t)row * N + col) = lw;
            split2(d2, d3, hw, lw);
            *(uint32_t*)(Ch + (size_t)(row + 8) * N + col) = hw;
            *(uint32_t*)(Cl + (size_t)(row + 8) * N + col) = lw;
        }
    }
}

// ===========================================================================
// Flash attention v6 (reverted round-10 version: Q from smem, no hoist).
// ===========================================================================
#define F_QH   0
#define F_QL   18432
#define F_ST0  36864
#define F_ST1  73728
#define F_KH   0
#define F_KL   9216
#define F_VH   18432
#define F_VL   27648
#define F_MSK0 110592
#define F_MSK1 110848
#define F_TOTAL 111104

__global__ __launch_bounds__(128, 2)
void flash_mma6(const __nv_bfloat16* __restrict__ q_hi,
                const __nv_bfloat16* __restrict__ q_lo,
                const __nv_bfloat16* __restrict__ kv_hi,
                const __nv_bfloat16* __restrict__ kv_lo,
                __nv_bfloat16* __restrict__ attn_hi,
                __nv_bfloat16* __restrict__ attn_lo)
{
    extern __shared__ char sm[];
    uint32_t sbase = smem_u32(sm);
    float* msk0 = (float*)(sm + F_MSK0);
    float* msk1 = (float*)(sm + F_MSK1);
    int tid = threadIdx.x;
    int lane = tid & 31;
    int w = tid >> 5;
    int b = blockIdx.z;
    int h = blockIdx.y;
    int q0 = blockIdx.x * 128;
    int qbase = w * 32;

    int cnt = g_kcount[b];
    int ntiles = (cnt + 63) >> 6;

#pragma unroll
    for (int it = 0; it < 8; it++) {
        int idx = tid + it * 128;
        int row = idx >> 3, cg = idx & 7;
        size_t g = (size_t)((q0 + row) * 2 + b) * E_DIM + h * 64 + cg * 8;
        uint32_t d = sbase + (uint32_t)(row * 144 + cg * 16);
        cp_async16(d + F_QH, q_hi + g);
        cp_async16(d + F_QL, q_lo + g);
    }
    cp_commit();

    auto issue_kv = [&](int s0, uint32_t st) {
#pragma unroll
        for (int it = 0; it < 4; it++) {
            int idx = tid + it * 128;
            int row = idx >> 3, cg = idx & 7;
            size_t g = (size_t)(b * T_DIM + s0 + row) * (2 * E_DIM) + h * 64 + cg * 8;
            uint32_t d = sbase + st + (uint32_t)(row * 144 + cg * 16);
            cp_async16(d + F_KH, kv_hi + g);
            cp_async16(d + F_KL, kv_lo + g);
            cp_async16(d + F_VH, kv_hi + g + E_DIM);
            cp_async16(d + F_VL, kv_lo + g + E_DIM);
        }
    };

    issue_kv(0, F_ST0);
    if (tid < 64)
        msk0[tid] = g_kmask[b * T_DIM + tid];
    cp_commit();

    float l[2][2];
    l[0][0] = l[0][1] = l[1][0] = l[1][1] = 0.f;
    float o[2][8][4];
#pragma unroll
    for (int mf = 0; mf < 2; mf++)
#pragma unroll
        for (int nf = 0; nf < 8; nf++)
#pragma unroll
            for (int c = 0; c < 4; c++) o[mf][nf][c] = 0.f;

    for (int c = 0; c < ntiles; c++) {
        uint32_t st = (c & 1) ? F_ST1 : F_ST0;
        float* mk = (c & 1) ? msk1 : msk0;
        if (c + 1 < ntiles) {
            issue_kv((c + 1) * 64, ((c + 1) & 1) ? F_ST1 : F_ST0);
            float* mkn = ((c + 1) & 1) ? msk1 : msk0;
            if (tid < 64)
                mkn[tid] = g_kmask[b * T_DIM + (c + 1) * 64 + tid];
            cp_commit();
            cp_wait<1>();
        } else {
            cp_wait<0>();
        }
        __syncthreads();

        // ---- S = Q K^T, pass-major ----
        float acc[2][8][4];
#pragma unroll
        for (int mf = 0; mf < 2; mf++)
#pragma unroll
            for (int nf = 0; nf < 8; nf++)
#pragma unroll
                for (int cc = 0; cc < 4; cc++) acc[mf][nf][cc] = 0.f;

#pragma unroll
        for (int kf = 0; kf < 4; kf++) {
            uint32_t qhi[2][4], qlo[2][4];
#pragma unroll
            for (int mf = 0; mf < 2; mf++) {
                int row = qbase + mf * 16 + (lane & 15);
                int col = kf * 16 + (lane >> 4) * 8;
                uint32_t ad = sbase + (uint32_t)(row * 144 + col * 2);
                ldmatrix_x4(qhi[mf][0], qhi[mf][1], qhi[mf][2], qhi[mf][3], ad + F_QH);
                ldmatrix_x4(qlo[mf][0], qlo[mf][1], qlo[mf][2], qlo[mf][3], ad + F_QL);
            }
            uint32_t khi[4][4], klo[4][4];
#pragma unroll
            for (int np = 0; np < 4; np++) {
                int row = (np * 2 + (lane >> 4)) * 8 + (lane & 7);
                int col = kf * 16 + ((lane >> 3) & 1) * 8;
                uint32_t ad = sbase + st + (uint32_t)(row * 144 + col * 2);
                ldmatrix_x4(khi[np][0], khi[np][1], khi[np][2], khi[np][3], ad + F_KH);
                ldmatrix_x4(klo[np][0], klo[np][1], klo[np][2], klo[np][3], ad + F_KL);
            }
#pragma unroll
            for (int mf = 0; mf < 2; mf++)
#pragma unroll
                for (int np = 0; np < 4; np++) {
                    mma_bf16(acc[mf][np * 2],     qhi[mf], khi[np]);
                    mma_bf16(acc[mf][np * 2 + 1], qhi[mf], khi[np] + 2);
                }
#pragma unroll
            for (int mf = 0; mf < 2; mf++)
#pragma unroll
                for (int np = 0; np < 4; np++) {
                    mma_bf16(acc[mf][np * 2],     qhi[mf], klo[np]);
                    mma_bf16(acc[mf][np * 2 + 1], qhi[mf], klo[np] + 2);
                }
#pragma unroll
            for (int mf = 0; mf < 2; mf++)
#pragma unroll
                for (int np = 0; np < 4; np++) {
                    mma_bf16(acc[mf][np * 2],     qlo[mf], khi[np]);
                    mma_bf16(acc[mf][np * 2 + 1], qlo[mf], khi[np] + 2);
                }
        }

        // ---- pad-mask + exp (fixed reference m = 0) ----
#pragma unroll
        for (int mf = 0; mf < 2; mf++) {
            float rs1 = 0.f, rs2 = 0.f;
#pragma unroll
            for (int nf = 0; nf < 8; nf++) {
                float2 mv = *(float2*)&mk[nf * 8 + (lane & 3) * 2];
                float p0 = __expf(acc[mf][nf][0] + mv.x);
                float p1 = __expf(acc[mf][nf][1] + mv.y);
                float p2 = __expf(acc[mf][nf][2] + mv.x);
                float p3 = __expf(acc[mf][nf][3] + mv.y);
                acc[mf][nf][0] = p0; acc[mf][nf][1] = p1;
                acc[mf][nf][2] = p2; acc[mf][nf][3] = p3;
                rs1 += p0 + p1;
                rs2 += p2 + p3;
            }
            rs1 += __shfl_xor_sync(0xffffffffu, rs1, 1);
            rs1 += __shfl_xor_sync(0xffffffffu, rs1, 2);
            rs2 += __shfl_xor_sync(0xffffffffu, rs2, 1);
            rs2 += __shfl_xor_sync(0xffffffffu, rs2, 2);
            l[mf][0] += rs1;
            l[mf][1] += rs2;
        }

        // ---- O += P V, pass-major ----
#pragma unroll
        for (int kf = 0; kf < 4; kf++) {
            uint32_t phi[2][4], plo[2][4];
#pragma unroll
            for (int mf = 0; mf < 2; mf++) {
                split2(acc[mf][2 * kf][0],     acc[mf][2 * kf][1],     phi[mf][0], plo[mf][0]);
                split2(acc[mf][2 * kf][2],     acc[mf][2 * kf][3],     phi[mf][1], plo[mf][1]);
                split2(acc[mf][2 * kf + 1][0], acc[mf][2 * kf + 1][1], phi[mf][2], plo[mf][2]);
                split2(acc[mf][2 * kf + 1][2], acc[mf][2 * kf + 1][3], phi[mf][3], plo[mf][3]);
            }
            uint32_t vhi[4][4], vlo[4][4];
#pragma unroll
            for (int np = 0; np < 4; np++) {
                int row = kf * 16 + (lane & 15);
                int col = (np * 2 + (lane >> 4)) * 8;
                uint32_t ad = sbase + st + (uint32_t)(row * 144 + col * 2);
                ldmatrix_x4_trans(vhi[np][0], vhi[np][1], vhi[np][2], vhi[np][3], ad + F_VH);
                ldmatrix_x4_trans(vlo[np][0], vlo[np][1], vlo[np][2], vlo[np][3], ad + F_VL);
            }
#pragma unroll
            for (int mf = 0; mf < 2; mf++)
#pragma unroll
                for (int np = 0; np < 4; np++) {
                    mma_bf16(o[mf][np * 2],     phi[mf], vhi[np]);
                    mma_bf16(o[mf][np * 2 + 1], phi[mf], vhi[np] + 2);
                }
#pragma unroll
            for (int mf = 0; mf < 2; mf++)
#pragma unroll
                for (int np = 0; np < 4; np++) {
                    mma_bf16(o[mf][np * 2],     phi[mf], vlo[np]);
                    mma_bf16(o[mf][np * 2 + 1], phi[mf], vlo[np] + 2);
                }
#pragma unroll
            for (int mf = 0; mf < 2; mf++)
#pragma unroll
                for (int np = 0; np < 4; np++) {
                    mma_bf16(o[mf][np * 2],     plo[mf], vhi[np]);
                    mma_bf16(o[mf][np * 2 + 1], plo[mf], vhi[np] + 2);
                }
        }
        __syncthreads();
    }

    // ---- epilogue ----
#pragma unroll
    for (int mf = 0; mf < 2; mf++) {
        float inv1 = 1.f / l[mf][0];
        float inv2 = 1.f / l[mf][1];
        int t1 = q0 + qbase + mf * 16 + (lane >> 2);
        int t2 = t1 + 8;
#pragma unroll
        for (int nf = 0; nf < 8; nf++) {
            int d = h * 64 + nf * 8 + (lane & 3) * 2;
            size_t r1 = (size_t)(t1 * 2 + b) * E_DIM + d;
            size_t r2 = (size_t)(t2 * 2 + b) * E_DIM + d;
            uint32_t hw, lw;
            split2(o[mf][nf][0] * inv1, o[mf][nf][1] * inv1, hw, lw);
            *(uint32_t*)(attn_hi + r1) = hw;
            *(uint32_t*)(attn_lo + r1) = lw;
            split2(o[mf][nf][2] * inv2, o[mf][nf][3] * inv2, hw, lw);
            *(uint32_t*)(attn_hi + r2) = hw;
            *(uint32_t*)(attn_lo + r2) = lw;
        }
    }
}

// ===========================================================================
extern "C" void kernel_launch(void* const* d_in, const int* in_sizes, int n_in,
                              void* d_out, int out_size)
{
    const float* x      = (const float*)d_in[0];
    const float* w_in   = (const float*)d_in[1];
    const float* b_in   = (const float*)d_in[2];
    const float* w_out  = (const float*)d_in[3];
    const float* b_out  = (const float*)d_in[4];
    const void*  mask   = d_in[5];
    float* out = (float*)d_out;

    __nv_bfloat16 *x_hi, *x_lo, *win_hi, *win_lo, *wout_hi, *wout_lo;
    __nv_bfloat16 *q_hi, *q_lo, *kv_hi, *kv_lo, *attn_hi, *attn_lo;
    cudaGetSymbolAddress((void**)&x_hi, g_x_hi);
    cudaGetSymbolAddress((void**)&x_lo, g_x_lo);
    cudaGetSymbolAddress((void**)&win_hi, g_win_hi);
    cudaGetSymbolAddress((void**)&win_lo, g_win_lo);
    cudaGetSymbolAddress((void**)&wout_hi, g_wout_hi);
    cudaGetSymbolAddress((void**)&wout_lo, g_wout_lo);
    cudaGetSymbolAddress((void**)&q_hi, g_q_hi);
    cudaGetSymbolAddress((void**)&q_lo, g_q_lo);
    cudaGetSymbolAddress((void**)&kv_hi, g_kv_hi);
    cudaGetSymbolAddress((void**)&kv_lo, g_kv_lo);
    cudaGetSymbolAddress((void**)&attn_hi, g_attn_hi);
    cudaGetSymbolAddress((void**)&attn_lo, g_attn_lo);

    cudaFuncSetAttribute(gemm_dense,
                         cudaFuncAttributeMaxDynamicSharedMemorySize, G_TOTAL);
    cudaFuncSetAttribute(gemm_qkv,
                         cudaFuncAttributeMaxDynamicSharedMemorySize, G_TOTAL_RM);
    cudaFuncSetAttribute(flash_mma6,
                         cudaFuncAttributeMaxDynamicSharedMemorySize, F_TOTAL);

    // 0) mask prep + pre-split inputs
    mask_prep_kernel<<<1, 256>>>(mask);
    presplit_kernel<<<(MROWS * E_DIM / 4 + 255) / 256, 256>>>(x, x_hi, x_lo,
                                                              MROWS * E_DIM / 4);
    presplit_kernel<<<(3 * E_DIM * E_DIM / 4 + 255) / 256, 256>>>(
        w_in, win_hi, win_lo, 3 * E_DIM * E_DIM / 4);
    presplit_kernel<<<(E_DIM * E_DIM / 4 + 255) / 256, 256>>>(
        w_out, wout_hi, wout_lo, E_DIM * E_DIM / 4);

    // 1) fused q + kv projection (q scaled 0.125; kv compacted)
    {
        dim3 grid(16 + 32, MROWS / 128);
        gemm_qkv<<<grid, 256, G_TOTAL_RM>>>(x_hi, x_lo, win_hi, win_lo, b_in,
                                            q_hi, q_lo, kv_hi, kv_lo);
    }

    // 2) flash attention (compacted, contiguous K/V) -> split bf16 attn
    {
        dim3 grid(T_DIM / 128, H_DIM, B_DIM);
        flash_mma6<<<grid, 128, F_TOTAL>>>(q_hi, q_lo, kv_hi, kv_lo,
                                           attn_hi, attn_lo);
    }

    // 3) out = attn @ W_out^T + b_out   [4096 x 1024] fp32
    {
        dim3 grid(E_DIM / 64, MROWS / 128);
        gemm_dense<<<grid, 256, G_TOTAL>>>(attn_hi, attn_lo,
                                           wout_hi, wout_lo,
                                           b_out, out, E_DIM);
    }
}

// round 13
// speedup vs baseline: 1.0544x; 1.0075x over previous
#include <cuda_runtime.h>
#include <cuda_bf16.h>
#include <cstdint>
#include <cstddef>

#define T_DIM 2048
#define B_DIM 2
#define E_DIM 1024
#define H_DIM 16
#define MROWS (T_DIM * B_DIM)      // 4096
#define K_DIM 1024
#define NEG_INF_F (-1e24f)

// ---------------------------------------------------------------------------
// Scratch (no cudaMalloc allowed)
// ---------------------------------------------------------------------------
__device__ __nv_bfloat16 g_x_hi[(size_t)MROWS * E_DIM];
__device__ __nv_bfloat16 g_x_lo[(size_t)MROWS * E_DIM];
__device__ __nv_bfloat16 g_win_hi[(size_t)3 * E_DIM * E_DIM];
__device__ __nv_bfloat16 g_win_lo[(size_t)3 * E_DIM * E_DIM];
__device__ __nv_bfloat16 g_wout_hi[(size_t)E_DIM * E_DIM];
__device__ __nv_bfloat16 g_wout_lo[(size_t)E_DIM * E_DIM];
__device__ __nv_bfloat16 g_q_hi[(size_t)MROWS * E_DIM];
__device__ __nv_bfloat16 g_q_lo[(size_t)MROWS * E_DIM];
// compacted K|V: row = b*2048 + compact_j, cols [0,1024)=K, [1024,2048)=V
__device__ __nv_bfloat16 g_kv_hi[(size_t)MROWS * 2 * E_DIM];
__device__ __nv_bfloat16 g_kv_lo[(size_t)MROWS * 2 * E_DIM];
__device__ __nv_bfloat16 g_attn_hi[(size_t)MROWS * E_DIM];
__device__ __nv_bfloat16 g_attn_lo[(size_t)MROWS * E_DIM];
__device__ unsigned char g_mask[MROWS];
__device__ int   g_kidx[B_DIM * T_DIM];
__device__ int   g_kcount[B_DIM];
__device__ float g_kmask[B_DIM * T_DIM];

// ===========================================================================
// PTX helpers
// ===========================================================================
__device__ __forceinline__ uint32_t smem_u32(const void* p) {
    uint32_t a;
    asm("{ .reg .u64 t; cvta.to.shared.u64 t, %1; cvt.u32.u64 %0, t; }"
        : "=r"(a) : "l"(p));
    return a;
}
__device__ __forceinline__ void ldmatrix_x4(uint32_t& r0, uint32_t& r1,
                                            uint32_t& r2, uint32_t& r3,
                                            uint32_t addr) {
    asm volatile("ldmatrix.sync.aligned.m8n8.x4.shared.b16 {%0,%1,%2,%3}, [%4];"
                 : "=r"(r0), "=r"(r1), "=r"(r2), "=r"(r3) : "r"(addr));
}
__device__ __forceinline__ void ldmatrix_x4_trans(uint32_t& r0, uint32_t& r1,
                                                  uint32_t& r2, uint32_t& r3,
                                                  uint32_t addr) {
    asm volatile("ldmatrix.sync.aligned.m8n8.x4.trans.shared.b16 {%0,%1,%2,%3}, [%4];"
                 : "=r"(r0), "=r"(r1), "=r"(r2), "=r"(r3) : "r"(addr));
}
__device__ __forceinline__ void mma_bf16(float* d, const uint32_t* a,
                                         const uint32_t* b) {
    asm("mma.sync.aligned.m16n8k16.row.col.f32.bf16.bf16.f32 "
        "{%0,%1,%2,%3}, {%4,%5,%6,%7}, {%8,%9}, {%0,%1,%2,%3};"
        : "+f"(d[0]), "+f"(d[1]), "+f"(d[2]), "+f"(d[3])
        : "r"(a[0]), "r"(a[1]), "r"(a[2]), "r"(a[3]), "r"(b[0]), "r"(b[1]));
}
__device__ __forceinline__ void cp_async16(uint32_t dst, const void* src) {
    asm volatile("cp.async.cg.shared.global [%0], [%1], 16;" :: "r"(dst), "l"(src));
}
__device__ __forceinline__ void cp_commit() {
    asm volatile("cp.async.commit_group;" ::: "memory");
}
template<int N> __device__ __forceinline__ void cp_wait() {
    asm volatile("cp.async.wait_group %0;" :: "n"(N) : "memory");
}

// Fast split: hi = truncated-to-bf16 pair via PRMT (1 instr), residuals exact
// in fp32 (same-exponent subtraction), lo = single cvt.rn.bf16x2.f32.
// Pair error ~2^-17 relative, same as the rn/rn split.
__device__ __forceinline__ void split2(float x, float y,
                                       uint32_t& hi, uint32_t& lo) {
    uint32_t xi = __float_as_uint(x);
    uint32_t yi = __float_as_uint(y);
    asm("prmt.b32 %0, %1, %2, 0x7632;" : "=r"(hi) : "r"(xi), "r"(yi));
    float hx = __uint_as_float(xi & 0xFFFF0000u);
    float hy = __uint_as_float(yi & 0xFFFF0000u);
    float rx = x - hx;
    float ry = y - hy;
    asm("cvt.rn.bf16x2.f32 %0, %1, %2;" : "=r"(lo) : "f"(ry), "f"(rx));
}

// ===========================================================================
// Mask prep (single kernel, single block): detect dtype, expand, compact.
// ===========================================================================
__global__ void mask_prep_kernel(const void* __restrict__ mv)
{
    const unsigned char* m8 = (const unsigned char*)mv;
    __shared__ int s_nz, s_f32;
    int tid = threadIdx.x;
    if (tid == 0) { s_nz = 0; s_f32 = 0; }
    __syncthreads();
    int nz = 0, f32 = 0;
    for (int i = tid; i < MROWS; i += 256) {
        unsigned char v = m8[i];
        if ((i & 3) != 0 && v != 0) nz = 1;
        if ((i & 3) == 3 && v == 0x3F) f32 = 1;
    }
    if (nz)  atomicOr(&s_nz, 1);
    if (f32) atomicOr(&s_f32, 1);
    __syncthreads();
    int mode = s_f32 ? 2 : (s_nz ? 0 : 1);
    for (int i = tid; i < MROWS; i += 256) {
        unsigned char r;
        if (mode == 0)      r = m8[i] != 0;
        else if (mode == 1) r = ((const int*)mv)[i] != 0;
        else                r = ((const float*)mv)[i] != 0.0f;
        g_mask[i] = r;
    }
    __syncthreads();
    if (tid < 64) {
        int b = tid >> 5, lane = tid & 31;
        int base = 0;
        for (int j0 = 0; j0 < T_DIM; j0 += 32) {
            int t = j0 + lane;
            int keep = g_mask[t * B_DIM + b] ? 0 : 1;
            unsigned bal = __ballot_sync(0xffffffffu, keep);
            int pre = __popc(bal & ((1u << lane) - 1));
            if (keep) g_kidx[b * T_DIM + base + pre] = t;
            base += __popc(bal);
        }
        if (lane == 0) g_kcount[b] = base;
        for (int j = base + lane; j < T_DIM; j += 32)
            g_kidx[b * T_DIM + j] = 0;
        for (int j = lane; j < T_DIM; j += 32)
            g_kmask[b * T_DIM + j] = (j < base) ? 0.f : NEG_INF_F;
    }
}

// ===========================================================================
// Combined pre-split of x, w_in, w_out (one launch)
// ===========================================================================
#define N4_X   (MROWS * E_DIM / 4)               // 1048576
#define N4_WIN (3 * E_DIM * E_DIM / 4)           // 786432
#define N4_WOUT (E_DIM * E_DIM / 4)              // 262144
#define N4_TOTAL (N4_X + N4_WIN + N4_WOUT)

__global__ void presplit3_kernel(const float* __restrict__ x,
                                 const float* __restrict__ win,
                                 const float* __restrict__ wout,
                                 __nv_bfloat16* __restrict__ xh,
                                 __nv_bfloat16* __restrict__ xl,
                                 __nv_bfloat16* __restrict__ wh,
                                 __nv_bfloat16* __restrict__ wl,
                                 __nv_bfloat16* __restrict__ oh,
                                 __nv_bfloat16* __restrict__ ol)
{
    int i = blockIdx.x * 256 + threadIdx.x;
    if (i >= N4_TOTAL) return;
    const float* src;
    __nv_bfloat16 *hi, *lo;
    int j;
    if (i < N4_X)              { src = x;    j = i;                 hi = xh; lo = xl; }
    else if (i < N4_X + N4_WIN){ src = win;  j = i - N4_X;          hi = wh; lo = wl; }
    else                       { src = wout; j = i - N4_X - N4_WIN; hi = oh; lo = ol; }
    float4 v = ((const float4*)src)[j];
    uint32_t h0, l0, h1, l1;
    split2(v.x, v.y, h0, l0);
    split2(v.z, v.w, h1, l1);
    uint2 hh, ll;
    hh.x = h0; hh.y = h1;
    ll.x = l0; ll.y = l1;
    ((uint2*)hi)[j] = hh;
    ((uint2*)lo)[j] = ll;
}

// ===========================================================================
// Shared GEMM smem layout
// ===========================================================================
#define GST   55296
#define G_AH  0
#define G_AL  18432
#define G_BH  36864
#define G_BL  46080
#define G_TOTAL (2 * GST)
#define G_RM  G_TOTAL
#define G_TOTAL_RM (G_TOTAL + 512)

// ===========================================================================
// Dense 2-stage split-bf16 HMMA GEMM (out projection)
// ===========================================================================
__global__ __launch_bounds__(256, 2)
void gemm_dense(const __nv_bfloat16* __restrict__ Ah,
                const __nv_bfloat16* __restrict__ Al,
                const __nv_bfloat16* __restrict__ Bh,
                const __nv_bfloat16* __restrict__ Bl,
                const float* __restrict__ bias,
                float* __restrict__ C, int N)
{
    extern __shared__ char sm[];
    uint32_t sbase = smem_u32(sm);
    int tid  = threadIdx.x;
    int lane = tid & 31;
    int wid  = tid >> 5;
    int warp_m = wid & 3;
    int warp_n = wid >> 2;
    int m0 = blockIdx.y * 128;
    int n0 = blockIdx.x * 64;

    float acc[2][4][4];
#pragma unroll
    for (int i = 0; i < 2; i++)
#pragma unroll
        for (int j = 0; j < 4; j++)
#pragma unroll
            for (int c = 0; c < 4; c++) acc[i][j][c] = 0.f;

    auto issue = [&](int k0, uint32_t st) {
#pragma unroll
        for (int it = 0; it < 4; it++) {
            int idx = tid + it * 256;
            int row = idx >> 3, cg = idx & 7;
            size_t g = (size_t)(m0 + row) * K_DIM + k0 + cg * 8;
            uint32_t d = sbase + st + (uint32_t)(row * 144 + cg * 16);
            cp_async16(d + G_AH, Ah + g);
            cp_async16(d + G_AL, Al + g);
        }
#pragma unroll
        for (int it = 0; it < 2; it++) {
            int idx = tid + it * 256;
            int row = idx >> 3, cg = idx & 7;
            size_t g = (size_t)(n0 + row) * K_DIM + k0 + cg * 8;
            uint32_t d = sbase + st + (uint32_t)(row * 144 + cg * 16);
            cp_async16(d + G_BH, Bh + g);
            cp_async16(d + G_BL, Bl + g);
        }
    };

    issue(0, 0);
    cp_commit();

    for (int c = 0; c < 16; c++) {
        uint32_t st = (c & 1) ? GST : 0;
        if (c + 1 < 16) {
            issue((c + 1) * 64, ((c + 1) & 1) ? GST : 0);
            cp_commit();
            cp_wait<1>();
        } else {
            cp_wait<0>();
        }
        __syncthreads();

#pragma unroll
        for (int ks = 0; ks < 4; ks++) {
            uint32_t ahi[2][4], alo[2][4];
#pragma unroll
            for (int mf = 0; mf < 2; mf++) {
                int row = warp_m * 32 + mf * 16 + (lane & 15);
                int col = ks * 16 + (lane >> 4) * 8;
                uint32_t ad = sbase + st + (uint32_t)(row * 144 + col * 2);
                ldmatrix_x4(ahi[mf][0], ahi[mf][1], ahi[mf][2], ahi[mf][3], ad + G_AH);
                ldmatrix_x4(alo[mf][0], alo[mf][1], alo[mf][2], alo[mf][3], ad + G_AL);
            }
            uint32_t bhi[4][2], blo[4][2];
#pragma unroll
            for (int np = 0; np < 2; np++) {
                int row = warp_n * 32 + (np * 2 + (lane >> 4)) * 8 + (lane & 7);
                int col = ks * 16 + ((lane >> 3) & 1) * 8;
                uint32_t ad = sbase + st + (uint32_t)(row * 144 + col * 2);
                uint32_t r0, r1, r2, r3;
                ldmatrix_x4(r0, r1, r2, r3, ad + G_BH);
                bhi[np * 2][0] = r0; bhi[np * 2][1] = r1;
                bhi[np * 2 + 1][0] = r2; bhi[np * 2 + 1][1] = r3;
                ldmatrix_x4(r0, r1, r2, r3, ad + G_BL);
                blo[np * 2][0] = r0; blo[np * 2][1] = r1;
                blo[np * 2 + 1][0] = r2; blo[np * 2 + 1][1] = r3;
            }
#pragma unroll
            for (int mf = 0; mf < 2; mf++)
#pragma unroll
                for (int nf = 0; nf < 4; nf++)
                    mma_bf16(acc[mf][nf], ahi[mf], bhi[nf]);
#pragma unroll
            for (int mf = 0; mf < 2; mf++)
#pragma unroll
                for (int nf = 0; nf < 4; nf++)
                    mma_bf16(acc[mf][nf], ahi[mf], blo[nf]);
#pragma unroll
            for (int mf = 0; mf < 2; mf++)
#pragma unroll
                for (int nf = 0; nf < 4; nf++)
                    mma_bf16(acc[mf][nf], alo[mf], bhi[nf]);
        }
        __syncthreads();
    }

#pragma unroll
    for (int mf = 0; mf < 2; mf++) {
#pragma unroll
        for (int nf = 0; nf < 4; nf++) {
            int row = m0 + warp_m * 32 + mf * 16 + (lane >> 2);
            int col = n0 + warp_n * 32 + nf * 8 + (lane & 3) * 2;
            float b0 = bias[col], b1 = bias[col + 1];
            C[(size_t)row * N + col]           = acc[mf][nf][0] + b0;
            C[(size_t)row * N + col + 1]       = acc[mf][nf][1] + b1;
            C[(size_t)(row + 8) * N + col]     = acc[mf][nf][2] + b0;
            C[(size_t)(row + 8) * N + col + 1] = acc[mf][nf][3] + b1;
        }
    }
}

// ===========================================================================
// Fused q + kv projection GEMM (blockIdx.x < 16 -> q, else kv-compacted)
// ===========================================================================
__global__ __launch_bounds__(256, 2)
void gemm_qkv(const __nv_bfloat16* __restrict__ Ah,
              const __nv_bfloat16* __restrict__ Al,
              const __nv_bfloat16* __restrict__ Wh,
              const __nv_bfloat16* __restrict__ Wl,
              const float* __restrict__ bias,
              __nv_bfloat16* __restrict__ Qh,
              __nv_bfloat16* __restrict__ Ql,
              __nv_bfloat16* __restrict__ KVh,
              __nv_bfloat16* __restrict__ KVl)
{
    extern __shared__ char sm[];
    uint32_t sbase = smem_u32(sm);
    int* s_row = (int*)(sm + G_RM);
    int tid  = threadIdx.x;
    int lane = tid & 31;
    int wid  = tid >> 5;
    int warp_m = wid & 3;
    int warp_n = wid >> 2;
    int m0 = blockIdx.y * 128;
    bool is_q = blockIdx.x < 16;
    int n0 = is_q ? blockIdx.x * 64 : (blockIdx.x - 16) * 64;
    int wrow0 = is_q ? n0 : (E_DIM + n0);

    int b = 0, j0 = 0;
    if (!is_q) {
        b = (m0 >= T_DIM) ? 1 : 0;
        j0 = m0 - b * T_DIM;
        int cnt = g_kcount[b];
        if (j0 >= ((cnt + 63) & ~63)) return;
    }

    if (tid < 128)
        s_row[tid] = is_q ? (m0 + tid) : (g_kidx[b * T_DIM + j0 + tid] * 2 + b);
    __syncthreads();

    float acc[2][4][4];
#pragma unroll
    for (int i = 0; i < 2; i++)
#pragma unroll
        for (int j = 0; j < 4; j++)
#pragma unroll
            for (int c = 0; c < 4; c++) acc[i][j][c] = 0.f;

    auto issue = [&](int k0, uint32_t st) {
#pragma unroll
        for (int it = 0; it < 4; it++) {
            int idx = tid + it * 256;
            int row = idx >> 3, cg = idx & 7;
            size_t g = (size_t)s_row[row] * K_DIM + k0 + cg * 8;
            uint32_t d = sbase + st + (uint32_t)(row * 144 + cg * 16);
            cp_async16(d + G_AH, Ah + g);
            cp_async16(d + G_AL, Al + g);
        }
#pragma unroll
        for (int it = 0; it < 2; it++) {
            int idx = tid + it * 256;
            int row = idx >> 3, cg = idx & 7;
            size_t g = (size_t)(wrow0 + row) * K_DIM + k0 + cg * 8;
            uint32_t d = sbase + st + (uint32_t)(row * 144 + cg * 16);
            cp_async16(d + G_BH, Wh + g);
            cp_async16(d + G_BL, Wl + g);
        }
    };

    issue(0, 0);
    cp_commit();

    for (int c = 0; c < 16; c++) {
        uint32_t st = (c & 1) ? GST : 0;
        if (c + 1 < 16) {
            issue((c + 1) * 64, ((c + 1) & 1) ? GST : 0);
            cp_commit();
            cp_wait<1>();
        } else {
            cp_wait<0>();
        }
        __syncthreads();

#pragma unroll
        for (int ks = 0; ks < 4; ks++) {
            uint32_t ahi[2][4], alo[2][4];
#pragma unroll
            for (int mf = 0; mf < 2; mf++) {
                int row = warp_m * 32 + mf * 16 + (lane & 15);
                int col = ks * 16 + (lane >> 4) * 8;
                uint32_t ad = sbase + st + (uint32_t)(row * 144 + col * 2);
                ldmatrix_x4(ahi[mf][0], ahi[mf][1], ahi[mf][2], ahi[mf][3], ad + G_AH);
                ldmatrix_x4(alo[mf][0], alo[mf][1], alo[mf][2], alo[mf][3], ad + G_AL);
            }
            uint32_t bhi[4][2], blo[4][2];
#pragma unroll
            for (int np = 0; np < 2; np++) {
                int row = warp_n * 32 + (np * 2 + (lane >> 4)) * 8 + (lane & 7);
                int col = ks * 16 + ((lane >> 3) & 1) * 8;
                uint32_t ad = sbase + st + (uint32_t)(row * 144 + col * 2);
                uint32_t r0, r1, r2, r3;
                ldmatrix_x4(r0, r1, r2, r3, ad + G_BH);
                bhi[np * 2][0] = r0; bhi[np * 2][1] = r1;
                bhi[np * 2 + 1][0] = r2; bhi[np * 2 + 1][1] = r3;
                ldmatrix_x4(r0, r1, r2, r3, ad + G_BL);
                blo[np * 2][0] = r0; blo[np * 2][1] = r1;
                blo[np * 2 + 1][0] = r2; blo[np * 2 + 1][1] = r3;
            }
#pragma unroll
            for (int mf = 0; mf < 2; mf++)
#pragma unroll
                for (int nf = 0; nf < 4; nf++)
                    mma_bf16(acc[mf][nf], ahi[mf], bhi[nf]);
#pragma unroll
            for (int mf = 0; mf < 2; mf++)
#pragma unroll
                for (int nf = 0; nf < 4; nf++)
                    mma_bf16(acc[mf][nf], ahi[mf], blo[nf]);
#pragma unroll
            for (int mf = 0; mf < 2; mf++)
#pragma unroll
                for (int nf = 0; nf < 4; nf++)
                    mma_bf16(acc[mf][nf], alo[mf], bhi[nf]);
        }
        __syncthreads();
    }

    int N = is_q ? E_DIM : 2 * E_DIM;
    __nv_bfloat16* Ch = is_q ? Qh : KVh;
    __nv_bfloat16* Cl = is_q ? Ql : KVl;
    float sc = is_q ? 0.125f : 1.0f;
#pragma unroll
    for (int mf = 0; mf < 2; mf++) {
#pragma unroll
        for (int nf = 0; nf < 4; nf++) {
            int row = m0 + warp_m * 32 + mf * 16 + (lane >> 2);
            int col = n0 + warp_n * 32 + nf * 8 + (lane & 3) * 2;
            int bcol = wrow0 + warp_n * 32 + nf * 8 + (lane & 3) * 2;
            float b0 = bias[bcol], b1 = bias[bcol + 1];
            float d0 = (acc[mf][nf][0] + b0) * sc;
            float d1 = (acc[mf][nf][1] + b1) * sc;
            float d2 = (acc[mf][nf][2] + b0) * sc;
            float d3 = (acc[mf][nf][3] + b1) * sc;
            uint32_t hw, lw;
            split2(d0, d1, hw, lw);
            *(uint32_t*)(Ch + (size_t)row * N + col) = hw;
            *(uint32_t*)(Cl + (size_t)row * N + col) = lw;
            split2(d2, d3, hw, lw);
            *(uint32_t*)(Ch + (size_t)(row + 8) * N + col) = hw;
            *(uint32_t*)(Cl + (size_t)(row + 8) * N + col) = lw;
        }
    }
}

// ===========================================================================
// Flash attention v6 (Q from smem) with fast P-split.
// ===========================================================================
#define F_QH   0
#define F_QL   18432
#define F_ST0  36864
#define F_ST1  73728
#define F_KH   0
#define F_KL   9216
#define F_VH   18432
#define F_VL   27648
#define F_MSK0 110592
#define F_MSK1 110848
#define F_TOTAL 111104

__global__ __launch_bounds__(128, 2)
void flash_mma6(const __nv_bfloat16* __restrict__ q_hi,
                const __nv_bfloat16* __restrict__ q_lo,
                const __nv_bfloat16* __restrict__ kv_hi,
                const __nv_bfloat16* __restrict__ kv_lo,
                __nv_bfloat16* __restrict__ attn_hi,
                __nv_bfloat16* __restrict__ attn_lo)
{
    extern __shared__ char sm[];
    uint32_t sbase = smem_u32(sm);
    float* msk0 = (float*)(sm + F_MSK0);
    float* msk1 = (float*)(sm + F_MSK1);
    int tid = threadIdx.x;
    int lane = tid & 31;
    int w = tid >> 5;
    int b = blockIdx.z;
    int h = blockIdx.y;
    int q0 = blockIdx.x * 128;
    int qbase = w * 32;

    int cnt = g_kcount[b];
    int ntiles = (cnt + 63) >> 6;

#pragma unroll
    for (int it = 0; it < 8; it++) {
        int idx = tid + it * 128;
        int row = idx >> 3, cg = idx & 7;
        size_t g = (size_t)((q0 + row) * 2 + b) * E_DIM + h * 64 + cg * 8;
        uint32_t d = sbase + (uint32_t)(row * 144 + cg * 16);
        cp_async16(d + F_QH, q_hi + g);
        cp_async16(d + F_QL, q_lo + g);
    }
    cp_commit();

    auto issue_kv = [&](int s0, uint32_t st) {
#pragma unroll
        for (int it = 0; it < 4; it++) {
            int idx = tid + it * 128;
            int row = idx >> 3, cg = idx & 7;
            size_t g = (size_t)(b * T_DIM + s0 + row) * (2 * E_DIM) + h * 64 + cg * 8;
            uint32_t d = sbase + st + (uint32_t)(row * 144 + cg * 16);
            cp_async16(d + F_KH, kv_hi + g);
            cp_async16(d + F_KL, kv_lo + g);
            cp_async16(d + F_VH, kv_hi + g + E_DIM);
            cp_async16(d + F_VL, kv_lo + g + E_DIM);
        }
    };

    issue_kv(0, F_ST0);
    if (tid < 64)
        msk0[tid] = g_kmask[b * T_DIM + tid];
    cp_commit();

    float l[2][2];
    l[0][0] = l[0][1] = l[1][0] = l[1][1] = 0.f;
    float o[2][8][4];
#pragma unroll
    for (int mf = 0; mf < 2; mf++)
#pragma unroll
        for (int nf = 0; nf < 8; nf++)
#pragma unroll
            for (int c = 0; c < 4; c++) o[mf][nf][c] = 0.f;

    for (int c = 0; c < ntiles; c++) {
        uint32_t st = (c & 1) ? F_ST1 : F_ST0;
        float* mk = (c & 1) ? msk1 : msk0;
        if (c + 1 < ntiles) {
            issue_kv((c + 1) * 64, ((c + 1) & 1) ? F_ST1 : F_ST0);
            float* mkn = ((c + 1) & 1) ? msk1 : msk0;
            if (tid < 64)
                mkn[tid] = g_kmask[b * T_DIM + (c + 1) * 64 + tid];
            cp_commit();
            cp_wait<1>();
        } else {
            cp_wait<0>();
        }
        __syncthreads();

        // ---- S = Q K^T, pass-major ----
        float acc[2][8][4];
#pragma unroll
        for (int mf = 0; mf < 2; mf++)
#pragma unroll
            for (int nf = 0; nf < 8; nf++)
#pragma unroll
                for (int cc = 0; cc < 4; cc++) acc[mf][nf][cc] = 0.f;

#pragma unroll
        for (int kf = 0; kf < 4; kf++) {
            uint32_t qhi[2][4], qlo[2][4];
#pragma unroll
            for (int mf = 0; mf < 2; mf++) {
                int row = qbase + mf * 16 + (lane & 15);
                int col = kf * 16 + (lane >> 4) * 8;
                uint32_t ad = sbase + (uint32_t)(row * 144 + col * 2);
                ldmatrix_x4(qhi[mf][0], qhi[mf][1], qhi[mf][2], qhi[mf][3], ad + F_QH);
                ldmatrix_x4(qlo[mf][0], qlo[mf][1], qlo[mf][2], qlo[mf][3], ad + F_QL);
            }
            uint32_t khi[4][4], klo[4][4];
#pragma unroll
            for (int np = 0; np < 4; np++) {
                int row = (np * 2 + (lane >> 4)) * 8 + (lane & 7);
                int col = kf * 16 + ((lane >> 3) & 1) * 8;
                uint32_t ad = sbase + st + (uint32_t)(row * 144 + col * 2);
                ldmatrix_x4(khi[np][0], khi[np][1], khi[np][2], khi[np][3], ad + F_KH);
                ldmatrix_x4(klo[np][0], klo[np][1], klo[np][2], klo[np][3], ad + F_KL);
            }
#pragma unroll
            for (int mf = 0; mf < 2; mf++)
#pragma unroll
                for (int np = 0; np < 4; np++) {
                    mma_bf16(acc[mf][np * 2],     qhi[mf], khi[np]);
                    mma_bf16(acc[mf][np * 2 + 1], qhi[mf], khi[np] + 2);
                }
#pragma unroll
            for (int mf = 0; mf < 2; mf++)
#pragma unroll
                for (int np = 0; np < 4; np++) {
                    mma_bf16(acc[mf][np * 2],     qhi[mf], klo[np]);
                    mma_bf16(acc[mf][np * 2 + 1], qhi[mf], klo[np] + 2);
                }
#pragma unroll
            for (int mf = 0; mf < 2; mf++)
#pragma unroll
                for (int np = 0; np < 4; np++) {
                    mma_bf16(acc[mf][np * 2],     qlo[mf], khi[np]);
                    mma_bf16(acc[mf][np * 2 + 1], qlo[mf], khi[np] + 2);
                }
        }

        // ---- pad-mask + exp (fixed reference m = 0) ----
#pragma unroll
        for (int mf = 0; mf < 2; mf++) {
            float rs1 = 0.f, rs2 = 0.f;
#pragma unroll
            for (int nf = 0; nf < 8; nf++) {
                float2 mv = *(float2*)&mk[nf * 8 + (lane & 3) * 2];
                float p0 = __expf(acc[mf][nf][0] + mv.x);
                float p1 = __expf(acc[mf][nf][1] + mv.y);
                float p2 = __expf(acc[mf][nf][2] + mv.x);
                float p3 = __expf(acc[mf][nf][3] + mv.y);
                acc[mf][nf][0] = p0; acc[mf][nf][1] = p1;
                acc[mf][nf][2] = p2; acc[mf][nf][3] = p3;
                rs1 += p0 + p1;
                rs2 += p2 + p3;
            }
            rs1 += __shfl_xor_sync(0xffffffffu, rs1, 1);
            rs1 += __shfl_xor_sync(0xffffffffu, rs1, 2);
            rs2 += __shfl_xor_sync(0xffffffffu, rs2, 1);
            rs2 += __shfl_xor_sync(0xffffffffu, rs2, 2);
            l[mf][0] += rs1;
            l[mf][1] += rs2;
        }

        // ---- O += P V, pass-major (fast P split) ----
#pragma unroll
        for (int kf = 0; kf < 4; kf++) {
            uint32_t phi[2][4], plo[2][4];
#pragma unroll
            for (int mf = 0; mf < 2; mf++) {
                split2(acc[mf][2 * kf][0],     acc[mf][2 * kf][1],     phi[mf][0], plo[mf][0]);
                split2(acc[mf][2 * kf][2],     acc[mf][2 * kf][3],     phi[mf][1], plo[mf][1]);
                split2(acc[mf][2 * kf + 1][0], acc[mf][2 * kf + 1][1], phi[mf][2], plo[mf][2]);
                split2(acc[mf][2 * kf + 1][2], acc[mf][2 * kf + 1][3], phi[mf][3], plo[mf][3]);
            }
            uint32_t vhi[4][4], vlo[4][4];
#pragma unroll
            for (int np = 0; np < 4; np++) {
                int row = kf * 16 + (lane & 15);
                int col = (np * 2 + (lane >> 4)) * 8;
                uint32_t ad = sbase + st + (uint32_t)(row * 144 + col * 2);
                ldmatrix_x4_trans(vhi[np][0], vhi[np][1], vhi[np][2], vhi[np][3], ad + F_VH);
                ldmatrix_x4_trans(vlo[np][0], vlo[np][1], vlo[np][2], vlo[np][3], ad + F_VL);
            }
#pragma unroll
            for (int mf = 0; mf < 2; mf++)
#pragma unroll
                for (int np = 0; np < 4; np++) {
                    mma_bf16(o[mf][np * 2],     phi[mf], vhi[np]);
                    mma_bf16(o[mf][np * 2 + 1], phi[mf], vhi[np] + 2);
                }
#pragma unroll
            for (int mf = 0; mf < 2; mf++)
#pragma unroll
                for (int np = 0; np < 4; np++) {
                    mma_bf16(o[mf][np * 2],     phi[mf], vlo[np]);
                    mma_bf16(o[mf][np * 2 + 1], phi[mf], vlo[np] + 2);
                }
#pragma unroll
            for (int mf = 0; mf < 2; mf++)
#pragma unroll
                for (int np = 0; np < 4; np++) {
                    mma_bf16(o[mf][np * 2],     plo[mf], vhi[np]);
                    mma_bf16(o[mf][np * 2 + 1], plo[mf], vhi[np] + 2);
                }
        }
        __syncthreads();
    }

    // ---- epilogue ----
#pragma unroll
    for (int mf = 0; mf < 2; mf++) {
        float inv1 = 1.f / l[mf][0];
        float inv2 = 1.f / l[mf][1];
        int t1 = q0 + qbase + mf * 16 + (lane >> 2);
        int t2 = t1 + 8;
#pragma unroll
        for (int nf = 0; nf < 8; nf++) {
            int d = h * 64 + nf * 8 + (lane & 3) * 2;
            size_t r1 = (size_t)(t1 * 2 + b) * E_DIM + d;
            size_t r2 = (size_t)(t2 * 2 + b) * E_DIM + d;
            uint32_t hw, lw;
            split2(o[mf][nf][0] * inv1, o[mf][nf][1] * inv1, hw, lw);
            *(uint32_t*)(attn_hi + r1) = hw;
            *(uint32_t*)(attn_lo + r1) = lw;
            split2(o[mf][nf][2] * inv2, o[mf][nf][3] * inv2, hw, lw);
            *(uint32_t*)(attn_hi + r2) = hw;
            *(uint32_t*)(attn_lo + r2) = lw;
        }
    }
}

// ===========================================================================
extern "C" void kernel_launch(void* const* d_in, const int* in_sizes, int n_in,
                              void* d_out, int out_size)
{
    const float* x      = (const float*)d_in[0];
    const float* w_in   = (const float*)d_in[1];
    const float* b_in   = (const float*)d_in[2];
    const float* w_out  = (const float*)d_in[3];
    const float* b_out  = (const float*)d_in[4];
    const void*  mask   = d_in[5];
    float* out = (float*)d_out;

    __nv_bfloat16 *x_hi, *x_lo, *win_hi, *win_lo, *wout_hi, *wout_lo;
    __nv_bfloat16 *q_hi, *q_lo, *kv_hi, *kv_lo, *attn_hi, *attn_lo;
    cudaGetSymbolAddress((void**)&x_hi, g_x_hi);
    cudaGetSymbolAddress((void**)&x_lo, g_x_lo);
    cudaGetSymbolAddress((void**)&win_hi, g_win_hi);
    cudaGetSymbolAddress((void**)&win_lo, g_win_lo);
    cudaGetSymbolAddress((void**)&wout_hi, g_wout_hi);
    cudaGetSymbolAddress((void**)&wout_lo, g_wout_lo);
    cudaGetSymbolAddress((void**)&q_hi, g_q_hi);
    cudaGetSymbolAddress((void**)&q_lo, g_q_lo);
    cudaGetSymbolAddress((void**)&kv_hi, g_kv_hi);
    cudaGetSymbolAddress((void**)&kv_lo, g_kv_lo);
    cudaGetSymbolAddress((void**)&attn_hi, g_attn_hi);
    cudaGetSymbolAddress((void**)&attn_lo, g_attn_lo);

    cudaFuncSetAttribute(gemm_dense,
                         cudaFuncAttributeMaxDynamicSharedMemorySize, G_TOTAL);
    cudaFuncSetAttribute(gemm_qkv,
                         cudaFuncAttributeMaxDynamicSharedMemorySize, G_TOTAL_RM);
    cudaFuncSetAttribute(flash_mma6,
                         cudaFuncAttributeMaxDynamicSharedMemorySize, F_TOTAL);

    // 0) mask prep + combined pre-split of x / w_in / w_out
    mask_prep_kernel<<<1, 256>>>(mask);
    presplit3_kernel<<<(N4_TOTAL + 255) / 256, 256>>>(
        x, w_in, w_out, x_hi, x_lo, win_hi, win_lo, wout_hi, wout_lo);

    // 1) fused q + kv projection (q scaled 0.125; kv compacted)
    {
        dim3 grid(16 + 32, MROWS / 128);
        gemm_qkv<<<grid, 256, G_TOTAL_RM>>>(x_hi, x_lo, win_hi, win_lo, b_in,
                                            q_hi, q_lo, kv_hi, kv_lo);
    }

    // 2) flash attention (compacted, contiguous K/V) -> split bf16 attn
    {
        dim3 grid(T_DIM / 128, H_DIM, B_DIM);
        flash_mma6<<<grid, 128, F_TOTAL>>>(q_hi, q_lo, kv_hi, kv_lo,
                                           attn_hi, attn_lo);
    }

    // 3) out = attn @ W_out^T + b_out   [4096 x 1024] fp32
    {
        dim3 grid(E_DIM / 64, MROWS / 128);
        gemm_dense<<<grid, 256, G_TOTAL>>>(attn_hi, attn_lo,
                                           wout_hi, wout_lo,
                                           b_out, out, E_DIM);
    }
}

// round 14
// speedup vs baseline: 1.1403x; 1.0815x over previous
#include <cuda_runtime.h>
#include <cuda_bf16.h>
#include <cstdint>
#include <cstddef>

#define T_DIM 2048
#define B_DIM 2
#define E_DIM 1024
#define H_DIM 16
#define MROWS (T_DIM * B_DIM)      // 4096
#define K_DIM 1024
#define NEG_INF_F (-1e24f)

// ---------------------------------------------------------------------------
// Scratch (no cudaMalloc allowed)
// ---------------------------------------------------------------------------
__device__ __nv_bfloat16 g_x_hi[(size_t)MROWS * E_DIM];
__device__ __nv_bfloat16 g_x_lo[(size_t)MROWS * E_DIM];
__device__ __nv_bfloat16 g_win_hi[(size_t)3 * E_DIM * E_DIM];
__device__ __nv_bfloat16 g_win_lo[(size_t)3 * E_DIM * E_DIM];
__device__ __nv_bfloat16 g_wout_hi[(size_t)E_DIM * E_DIM];
__device__ __nv_bfloat16 g_wout_lo[(size_t)E_DIM * E_DIM];
__device__ __nv_bfloat16 g_q_hi[(size_t)MROWS * E_DIM];
__device__ __nv_bfloat16 g_q_lo[(size_t)MROWS * E_DIM];
// compacted K|V: row = b*2048 + compact_j, cols [0,1024)=K, [1024,2048)=V
__device__ __nv_bfloat16 g_kv_hi[(size_t)MROWS * 2 * E_DIM];
__device__ __nv_bfloat16 g_kv_lo[(size_t)MROWS * 2 * E_DIM];
__device__ __nv_bfloat16 g_attn_hi[(size_t)MROWS * E_DIM];
__device__ __nv_bfloat16 g_attn_lo[(size_t)MROWS * E_DIM];
__device__ unsigned char g_mask[MROWS];
__device__ int   g_kidx[B_DIM * T_DIM];
__device__ int   g_kcount[B_DIM];
__device__ float g_kmask[B_DIM * T_DIM];

// ===========================================================================
// PTX helpers
// ===========================================================================
__device__ __forceinline__ uint32_t smem_u32(const void* p) {
    uint32_t a;
    asm("{ .reg .u64 t; cvta.to.shared.u64 t, %1; cvt.u32.u64 %0, t; }"
        : "=r"(a) : "l"(p));
    return a;
}
__device__ __forceinline__ void ldmatrix_x4(uint32_t& r0, uint32_t& r1,
                                            uint32_t& r2, uint32_t& r3,
                                            uint32_t addr) {
    asm volatile("ldmatrix.sync.aligned.m8n8.x4.shared.b16 {%0,%1,%2,%3}, [%4];"
                 : "=r"(r0), "=r"(r1), "=r"(r2), "=r"(r3) : "r"(addr));
}
__device__ __forceinline__ void ldmatrix_x4_trans(uint32_t& r0, uint32_t& r1,
                                                  uint32_t& r2, uint32_t& r3,
                                                  uint32_t addr) {
    asm volatile("ldmatrix.sync.aligned.m8n8.x4.trans.shared.b16 {%0,%1,%2,%3}, [%4];"
                 : "=r"(r0), "=r"(r1), "=r"(r2), "=r"(r3) : "r"(addr));
}
__device__ __forceinline__ void mma_bf16(float* d, const uint32_t* a,
                                         const uint32_t* b) {
    asm("mma.sync.aligned.m16n8k16.row.col.f32.bf16.bf16.f32 "
        "{%0,%1,%2,%3}, {%4,%5,%6,%7}, {%8,%9}, {%0,%1,%2,%3};"
        : "+f"(d[0]), "+f"(d[1]), "+f"(d[2]), "+f"(d[3])
        : "r"(a[0]), "r"(a[1]), "r"(a[2]), "r"(a[3]), "r"(b[0]), "r"(b[1]));
}
__device__ __forceinline__ void cp_async16(uint32_t dst, const void* src) {
    asm volatile("cp.async.cg.shared.global [%0], [%1], 16;" :: "r"(dst), "l"(src));
}
__device__ __forceinline__ void cp_commit() {
    asm volatile("cp.async.commit_group;" ::: "memory");
}
template<int N> __device__ __forceinline__ void cp_wait() {
    asm volatile("cp.async.wait_group %0;" :: "n"(N) : "memory");
}

// Fast split: hi = truncated bf16 pair via PRMT, residual exact in fp32,
// lo = single cvt.rn.bf16x2.f32. Pair error ~2^-17 relative.
__device__ __forceinline__ void split2(float x, float y,
                                       uint32_t& hi, uint32_t& lo) {
    uint32_t xi = __float_as_uint(x);
    uint32_t yi = __float_as_uint(y);
    asm("prmt.b32 %0, %1, %2, 0x7632;" : "=r"(hi) : "r"(xi), "r"(yi));
    float hx = __uint_as_float(xi & 0xFFFF0000u);
    float hy = __uint_as_float(yi & 0xFFFF0000u);
    float rx = x - hx;
    float ry = y - hy;
    asm("cvt.rn.bf16x2.f32 %0, %1, %2;" : "=r"(lo) : "f"(ry), "f"(rx));
}

// ===========================================================================
// Combined prep: presplit of x / w_in / w_out, plus mask prep in last block.
// ===========================================================================
#define N4_X   (MROWS * E_DIM / 4)
#define N4_WIN (3 * E_DIM * E_DIM / 4)
#define N4_WOUT (E_DIM * E_DIM / 4)
#define N4_TOTAL (N4_X + N4_WIN + N4_WOUT)
#define PREP_BLOCKS ((N4_TOTAL + 255) / 256 + 1)

__global__ void prep_kernel(const float* __restrict__ x,
                            const float* __restrict__ win,
                            const float* __restrict__ wout,
                            const void* __restrict__ mv,
                            __nv_bfloat16* __restrict__ xh,
                            __nv_bfloat16* __restrict__ xl,
                            __nv_bfloat16* __restrict__ wh,
                            __nv_bfloat16* __restrict__ wl,
                            __nv_bfloat16* __restrict__ oh,
                            __nv_bfloat16* __restrict__ ol)
{
    if (blockIdx.x == gridDim.x - 1) {
        // ---- mask prep block ----
        const unsigned char* m8 = (const unsigned char*)mv;
        __shared__ int s_nz, s_f32;
        int tid = threadIdx.x;
        if (tid == 0) { s_nz = 0; s_f32 = 0; }
        __syncthreads();
        int nz = 0, f32 = 0;
        for (int i = tid; i < MROWS; i += 256) {
            unsigned char v = m8[i];
            if ((i & 3) != 0 && v != 0) nz = 1;
            if ((i & 3) == 3 && v == 0x3F) f32 = 1;
        }
        if (nz)  atomicOr(&s_nz, 1);
        if (f32) atomicOr(&s_f32, 1);
        __syncthreads();
        int mode = s_f32 ? 2 : (s_nz ? 0 : 1);
        for (int i = tid; i < MROWS; i += 256) {
            unsigned char r;
            if (mode == 0)      r = m8[i] != 0;
            else if (mode == 1) r = ((const int*)mv)[i] != 0;
            else                r = ((const float*)mv)[i] != 0.0f;
            g_mask[i] = r;
        }
        __syncthreads();
        if (tid < 64) {
            int b = tid >> 5, lane = tid & 31;
            int base = 0;
            for (int j0 = 0; j0 < T_DIM; j0 += 32) {
                int t = j0 + lane;
                int keep = g_mask[t * B_DIM + b] ? 0 : 1;
                unsigned bal = __ballot_sync(0xffffffffu, keep);
                int pre = __popc(bal & ((1u << lane) - 1));
                if (keep) g_kidx[b * T_DIM + base + pre] = t;
                base += __popc(bal);
            }
            if (lane == 0) g_kcount[b] = base;
            for (int j = base + lane; j < T_DIM; j += 32)
                g_kidx[b * T_DIM + j] = 0;
            for (int j = lane; j < T_DIM; j += 32)
                g_kmask[b * T_DIM + j] = (j < base) ? 0.f : NEG_INF_F;
        }
        return;
    }

    int i = blockIdx.x * 256 + threadIdx.x;
    if (i >= N4_TOTAL) return;
    const float* src;
    __nv_bfloat16 *hi, *lo;
    int j;
    if (i < N4_X)              { src = x;    j = i;                 hi = xh; lo = xl; }
    else if (i < N4_X + N4_WIN){ src = win;  j = i - N4_X;          hi = wh; lo = wl; }
    else                       { src = wout; j = i - N4_X - N4_WIN; hi = oh; lo = ol; }
    float4 v = ((const float4*)src)[j];
    uint32_t h0, l0, h1, l1;
    split2(v.x, v.y, h0, l0);
    split2(v.z, v.w, h1, l1);
    uint2 hh, ll;
    hh.x = h0; hh.y = h1;
    ll.x = l0; ll.y = l1;
    ((uint2*)hi)[j] = hh;
    ((uint2*)lo)[j] = ll;
}

// ===========================================================================
// Shared GEMM smem layout
// ===========================================================================
#define GST   55296
#define G_AH  0
#define G_AL  18432
#define G_BH  36864
#define G_BL  46080
#define G_TOTAL (2 * GST)
#define G_RM  G_TOTAL
#define G_TOTAL_RM (G_TOTAL + 512)

// ===========================================================================
// Dense split-bf16 HMMA GEMM (out projection). Single barrier per K-chunk:
// [wait -> sync -> issue(next) -> compute].
// ===========================================================================
__global__ __launch_bounds__(256, 2)
void gemm_dense(const __nv_bfloat16* __restrict__ Ah,
                const __nv_bfloat16* __restrict__ Al,
                const __nv_bfloat16* __restrict__ Bh,
                const __nv_bfloat16* __restrict__ Bl,
                const float* __restrict__ bias,
                float* __restrict__ C, int N)
{
    extern __shared__ char sm[];
    uint32_t sbase = smem_u32(sm);
    int tid  = threadIdx.x;
    int lane = tid & 31;
    int wid  = tid >> 5;
    int warp_m = wid & 3;
    int warp_n = wid >> 2;
    int m0 = blockIdx.y * 128;
    int n0 = blockIdx.x * 64;

    float acc[2][4][4];
#pragma unroll
    for (int i = 0; i < 2; i++)
#pragma unroll
        for (int j = 0; j < 4; j++)
#pragma unroll
            for (int c = 0; c < 4; c++) acc[i][j][c] = 0.f;

    auto issue = [&](int k0, uint32_t st) {
#pragma unroll
        for (int it = 0; it < 4; it++) {
            int idx = tid + it * 256;
            int row = idx >> 3, cg = idx & 7;
            size_t g = (size_t)(m0 + row) * K_DIM + k0 + cg * 8;
            uint32_t d = sbase + st + (uint32_t)(row * 144 + cg * 16);
            cp_async16(d + G_AH, Ah + g);
            cp_async16(d + G_AL, Al + g);
        }
#pragma unroll
        for (int it = 0; it < 2; it++) {
            int idx = tid + it * 256;
            int row = idx >> 3, cg = idx & 7;
            size_t g = (size_t)(n0 + row) * K_DIM + k0 + cg * 8;
            uint32_t d = sbase + st + (uint32_t)(row * 144 + cg * 16);
            cp_async16(d + G_BH, Bh + g);
            cp_async16(d + G_BL, Bl + g);
        }
    };

    issue(0, 0);
    cp_commit();

    for (int c = 0; c < 16; c++) {
        uint32_t st = (c & 1) ? GST : 0;
        cp_wait<0>();
        __syncthreads();
        if (c + 1 < 16) {
            issue((c + 1) * 64, ((c + 1) & 1) ? GST : 0);
            cp_commit();
        }

#pragma unroll
        for (int ks = 0; ks < 4; ks++) {
            uint32_t ahi[2][4], alo[2][4];
#pragma unroll
            for (int mf = 0; mf < 2; mf++) {
                int row = warp_m * 32 + mf * 16 + (lane & 15);
                int col = ks * 16 + (lane >> 4) * 8;
                uint32_t ad = sbase + st + (uint32_t)(row * 144 + col * 2);
                ldmatrix_x4(ahi[mf][0], ahi[mf][1], ahi[mf][2], ahi[mf][3], ad + G_AH);
                ldmatrix_x4(alo[mf][0], alo[mf][1], alo[mf][2], alo[mf][3], ad + G_AL);
            }
            uint32_t bhi[4][2], blo[4][2];
#pragma unroll
            for (int np = 0; np < 2; np++) {
                int row = warp_n * 32 + (np * 2 + (lane >> 4)) * 8 + (lane & 7);
                int col = ks * 16 + ((lane >> 3) & 1) * 8;
                uint32_t ad = sbase + st + (uint32_t)(row * 144 + col * 2);
                uint32_t r0, r1, r2, r3;
                ldmatrix_x4(r0, r1, r2, r3, ad + G_BH);
                bhi[np * 2][0] = r0; bhi[np * 2][1] = r1;
                bhi[np * 2 + 1][0] = r2; bhi[np * 2 + 1][1] = r3;
                ldmatrix_x4(r0, r1, r2, r3, ad + G_BL);
                blo[np * 2][0] = r0; blo[np * 2][1] = r1;
                blo[np * 2 + 1][0] = r2; blo[np * 2 + 1][1] = r3;
            }
#pragma unroll
            for (int mf = 0; mf < 2; mf++)
#pragma unroll
                for (int nf = 0; nf < 4; nf++)
                    mma_bf16(acc[mf][nf], ahi[mf], bhi[nf]);
#pragma unroll
            for (int mf = 0; mf < 2; mf++)
#pragma unroll
                for (int nf = 0; nf < 4; nf++)
                    mma_bf16(acc[mf][nf], ahi[mf], blo[nf]);
#pragma unroll
            for (int mf = 0; mf < 2; mf++)
#pragma unroll
                for (int nf = 0; nf < 4; nf++)
                    mma_bf16(acc[mf][nf], alo[mf], bhi[nf]);
        }
    }

#pragma unroll
    for (int mf = 0; mf < 2; mf++) {
#pragma unroll
        for (int nf = 0; nf < 4; nf++) {
            int row = m0 + warp_m * 32 + mf * 16 + (lane >> 2);
            int col = n0 + warp_n * 32 + nf * 8 + (lane & 3) * 2;
            float b0 = bias[col], b1 = bias[col + 1];
            C[(size_t)row * N + col]           = acc[mf][nf][0] + b0;
            C[(size_t)row * N + col + 1]       = acc[mf][nf][1] + b1;
            C[(size_t)(row + 8) * N + col]     = acc[mf][nf][2] + b0;
            C[(size_t)(row + 8) * N + col + 1] = acc[mf][nf][3] + b1;
        }
    }
}

// ===========================================================================
// Fused q + kv projection GEMM (blockIdx.x < 16 -> q, else kv-compacted).
// Single barrier per K-chunk.
// ===========================================================================
__global__ __launch_bounds__(256, 2)
void gemm_qkv(const __nv_bfloat16* __restrict__ Ah,
              const __nv_bfloat16* __restrict__ Al,
              const __nv_bfloat16* __restrict__ Wh,
              const __nv_bfloat16* __restrict__ Wl,
              const float* __restrict__ bias,
              __nv_bfloat16* __restrict__ Qh,
              __nv_bfloat16* __restrict__ Ql,
              __nv_bfloat16* __restrict__ KVh,
              __nv_bfloat16* __restrict__ KVl)
{
    extern __shared__ char sm[];
    uint32_t sbase = smem_u32(sm);
    int* s_row = (int*)(sm + G_RM);
    int tid  = threadIdx.x;
    int lane = tid & 31;
    int wid  = tid >> 5;
    int warp_m = wid & 3;
    int warp_n = wid >> 2;
    int m0 = blockIdx.y * 128;
    bool is_q = blockIdx.x < 16;
    int n0 = is_q ? blockIdx.x * 64 : (blockIdx.x - 16) * 64;
    int wrow0 = is_q ? n0 : (E_DIM + n0);

    int b = 0, j0 = 0;
    if (!is_q) {
        b = (m0 >= T_DIM) ? 1 : 0;
        j0 = m0 - b * T_DIM;
        int cnt = g_kcount[b];
        if (j0 >= ((cnt + 63) & ~63)) return;
    }

    if (tid < 128)
        s_row[tid] = is_q ? (m0 + tid) : (g_kidx[b * T_DIM + j0 + tid] * 2 + b);
    __syncthreads();

    float acc[2][4][4];
#pragma unroll
    for (int i = 0; i < 2; i++)
#pragma unroll
        for (int j = 0; j < 4; j++)
#pragma unroll
            for (int c = 0; c < 4; c++) acc[i][j][c] = 0.f;

    auto issue = [&](int k0, uint32_t st) {
#pragma unroll
        for (int it = 0; it < 4; it++) {
            int idx = tid + it * 256;
            int row = idx >> 3, cg = idx & 7;
            size_t g = (size_t)s_row[row] * K_DIM + k0 + cg * 8;
            uint32_t d = sbase + st + (uint32_t)(row * 144 + cg * 16);
            cp_async16(d + G_AH, Ah + g);
            cp_async16(d + G_AL, Al + g);
        }
#pragma unroll
        for (int it = 0; it < 2; it++) {
            int idx = tid + it * 256;
            int row = idx >> 3, cg = idx & 7;
            size_t g = (size_t)(wrow0 + row) * K_DIM + k0 + cg * 8;
            uint32_t d = sbase + st + (uint32_t)(row * 144 + cg * 16);
            cp_async16(d + G_BH, Wh + g);
            cp_async16(d + G_BL, Wl + g);
        }
    };

    issue(0, 0);
    cp_commit();

    for (int c = 0; c < 16; c++) {
        uint32_t st = (c & 1) ? GST : 0;
        cp_wait<0>();
        __syncthreads();
        if (c + 1 < 16) {
            issue((c + 1) * 64, ((c + 1) & 1) ? GST : 0);
            cp_commit();
        }

#pragma unroll
        for (int ks = 0; ks < 4; ks++) {
            uint32_t ahi[2][4], alo[2][4];
#pragma unroll
            for (int mf = 0; mf < 2; mf++) {
                int row = warp_m * 32 + mf * 16 + (lane & 15);
                int col = ks * 16 + (lane >> 4) * 8;
                uint32_t ad = sbase + st + (uint32_t)(row * 144 + col * 2);
                ldmatrix_x4(ahi[mf][0], ahi[mf][1], ahi[mf][2], ahi[mf][3], ad + G_AH);
                ldmatrix_x4(alo[mf][0], alo[mf][1], alo[mf][2], alo[mf][3], ad + G_AL);
            }
            uint32_t bhi[4][2], blo[4][2];
#pragma unroll
            for (int np = 0; np < 2; np++) {
                int row = warp_n * 32 + (np * 2 + (lane >> 4)) * 8 + (lane & 7);
                int col = ks * 16 + ((lane >> 3) & 1) * 8;
                uint32_t ad = sbase + st + (uint32_t)(row * 144 + col * 2);
                uint32_t r0, r1, r2, r3;
                ldmatrix_x4(r0, r1, r2, r3, ad + G_BH);
                bhi[np * 2][0] = r0; bhi[np * 2][1] = r1;
                bhi[np * 2 + 1][0] = r2; bhi[np * 2 + 1][1] = r3;
                ldmatrix_x4(r0, r1, r2, r3, ad + G_BL);
                blo[np * 2][0] = r0; blo[np * 2][1] = r1;
                blo[np * 2 + 1][0] = r2; blo[np * 2 + 1][1] = r3;
            }
#pragma unroll
            for (int mf = 0; mf < 2; mf++)
#pragma unroll
                for (int nf = 0; nf < 4; nf++)
                    mma_bf16(acc[mf][nf], ahi[mf], bhi[nf]);
#pragma unroll
            for (int mf = 0; mf < 2; mf++)
#pragma unroll
                for (int nf = 0; nf < 4; nf++)
                    mma_bf16(acc[mf][nf], ahi[mf], blo[nf]);
#pragma unroll
            for (int mf = 0; mf < 2; mf++)
#pragma unroll
                for (int nf = 0; nf < 4; nf++)
                    mma_bf16(acc[mf][nf], alo[mf], bhi[nf]);
        }
    }

    int N = is_q ? E_DIM : 2 * E_DIM;
    __nv_bfloat16* Ch = is_q ? Qh : KVh;
    __nv_bfloat16* Cl = is_q ? Ql : KVl;
    float sc = is_q ? 0.125f : 1.0f;
#pragma unroll
    for (int mf = 0; mf < 2; mf++) {
#pragma unroll
        for (int nf = 0; nf < 4; nf++) {
            int row = m0 + warp_m * 32 + mf * 16 + (lane >> 2);
            int col = n0 + warp_n * 32 + nf * 8 + (lane & 3) * 2;
            int bcol = wrow0 + warp_n * 32 + nf * 8 + (lane & 3) * 2;
            float b0 = bias[bcol], b1 = bias[bcol + 1];
            float d0 = (acc[mf][nf][0] + b0) * sc;
            float d1 = (acc[mf][nf][1] + b1) * sc;
            float d2 = (acc[mf][nf][2] + b0) * sc;
            float d3 = (acc[mf][nf][3] + b1) * sc;
            uint32_t hw, lw;
            split2(d0, d1, hw, lw);
            *(uint32_t*)(Ch + (size_t)row * N + col) = hw;
            *(uint32_t*)(Cl + (size_t)row * N + col) = lw;
            split2(d2, d3, hw, lw);
            *(uint32_t*)(Ch + (size_t)(row + 8) * N + col) = hw;
            *(uint32_t*)(Cl + (size_t)(row + 8) * N + col) = lw;
        }
    }
}

// ===========================================================================
// Flash attention v8: single barrier per s-tile ([wait -> sync -> issue ->
// compute]); otherwise identical to the 437 us version.
// ===========================================================================
#define F_QH   0
#define F_QL   18432
#define F_ST0  36864
#define F_ST1  73728
#define F_KH   0
#define F_KL   9216
#define F_VH   18432
#define F_VL   27648
#define F_MSK0 110592
#define F_MSK1 110848
#define F_TOTAL 111104

__global__ __launch_bounds__(128, 2)
void flash_mma8(const __nv_bfloat16* __restrict__ q_hi,
                const __nv_bfloat16* __restrict__ q_lo,
                const __nv_bfloat16* __restrict__ kv_hi,
                const __nv_bfloat16* __restrict__ kv_lo,
                __nv_bfloat16* __restrict__ attn_hi,
                __nv_bfloat16* __restrict__ attn_lo)
{
    extern __shared__ char sm[];
    uint32_t sbase = smem_u32(sm);
    float* msk0 = (float*)(sm + F_MSK0);
    float* msk1 = (float*)(sm + F_MSK1);
    int tid = threadIdx.x;
    int lane = tid & 31;
    int w = tid >> 5;
    int b = blockIdx.z;
    int h = blockIdx.y;
    int q0 = blockIdx.x * 128;
    int qbase = w * 32;

    int cnt = g_kcount[b];
    int ntiles = (cnt + 63) >> 6;

#pragma unroll
    for (int it = 0; it < 8; it++) {
        int idx = tid + it * 128;
        int row = idx >> 3, cg = idx & 7;
        size_t g = (size_t)((q0 + row) * 2 + b) * E_DIM + h * 64 + cg * 8;
        uint32_t d = sbase + (uint32_t)(row * 144 + cg * 16);
        cp_async16(d + F_QH, q_hi + g);
        cp_async16(d + F_QL, q_lo + g);
    }

    auto issue_kv = [&](int s0, uint32_t st) {
#pragma unroll
        for (int it = 0; it < 4; it++) {
            int idx = tid + it * 128;
            int row = idx >> 3, cg = idx & 7;
            size_t g = (size_t)(b * T_DIM + s0 + row) * (2 * E_DIM) + h * 64 + cg * 8;
            uint32_t d = sbase + st + (uint32_t)(row * 144 + cg * 16);
            cp_async16(d + F_KH, kv_hi + g);
            cp_async16(d + F_KL, kv_lo + g);
            cp_async16(d + F_VH, kv_hi + g + E_DIM);
            cp_async16(d + F_VL, kv_lo + g + E_DIM);
        }
    };

    // stage Q + kv tile 0 together (one group)
    issue_kv(0, F_ST0);
    if (tid < 64)
        msk0[tid] = g_kmask[b * T_DIM + tid];
    cp_commit();

    float l[2][2];
    l[0][0] = l[0][1] = l[1][0] = l[1][1] = 0.f;
    float o[2][8][4];
#pragma unroll
    for (int mf = 0; mf < 2; mf++)
#pragma unroll
        for (int nf = 0; nf < 8; nf++)
#pragma unroll
            for (int c = 0; c < 4; c++) o[mf][nf][c] = 0.f;

    for (int c = 0; c < ntiles; c++) {
        uint32_t st = (c & 1) ? F_ST1 : F_ST0;
        float* mk = (c & 1) ? msk1 : msk0;
        cp_wait<0>();
        __syncthreads();
        if (c + 1 < ntiles) {
            issue_kv((c + 1) * 64, ((c + 1) & 1) ? F_ST1 : F_ST0);
            float* mkn = ((c + 1) & 1) ? msk1 : msk0;
            if (tid < 64)
                mkn[tid] = g_kmask[b * T_DIM + (c + 1) * 64 + tid];
            cp_commit();
        }

        // ---- S = Q K^T, pass-major ----
        float acc[2][8][4];
#pragma unroll
        for (int mf = 0; mf < 2; mf++)
#pragma unroll
            for (int nf = 0; nf < 8; nf++)
#pragma unroll
                for (int cc = 0; cc < 4; cc++) acc[mf][nf][cc] = 0.f;

#pragma unroll
        for (int kf = 0; kf < 4; kf++) {
            uint32_t qhi[2][4], qlo[2][4];
#pragma unroll
            for (int mf = 0; mf < 2; mf++) {
                int row = qbase + mf * 16 + (lane & 15);
                int col = kf * 16 + (lane >> 4) * 8;
                uint32_t ad = sbase + (uint32_t)(row * 144 + col * 2);
                ldmatrix_x4(qhi[mf][0], qhi[mf][1], qhi[mf][2], qhi[mf][3], ad + F_QH);
                ldmatrix_x4(qlo[mf][0], qlo[mf][1], qlo[mf][2], qlo[mf][3], ad + F_QL);
            }
            uint32_t khi[4][4], klo[4][4];
#pragma unroll
            for (int np = 0; np < 4; np++) {
                int row = (np * 2 + (lane >> 4)) * 8 + (lane & 7);
                int col = kf * 16 + ((lane >> 3) & 1) * 8;
                uint32_t ad = sbase + st + (uint32_t)(row * 144 + col * 2);
                ldmatrix_x4(khi[np][0], khi[np][1], khi[np][2], khi[np][3], ad + F_KH);
                ldmatrix_x4(klo[np][0], klo[np][1], klo[np][2], klo[np][3], ad + F_KL);
            }
#pragma unroll
            for (int mf = 0; mf < 2; mf++)
#pragma unroll
                for (int np = 0; np < 4; np++) {
                    mma_bf16(acc[mf][np * 2],     qhi[mf], khi[np]);
                    mma_bf16(acc[mf][np * 2 + 1], qhi[mf], khi[np] + 2);
                }
#pragma unroll
            for (int mf = 0; mf < 2; mf++)
#pragma unroll
                for (int np = 0; np < 4; np++) {
                    mma_bf16(acc[mf][np * 2],     qhi[mf], klo[np]);
                    mma_bf16(acc[mf][np * 2 + 1], qhi[mf], klo[np] + 2);
                }
#pragma unroll
            for (int mf = 0; mf < 2; mf++)
#pragma unroll
                for (int np = 0; np < 4; np++) {
                    mma_bf16(acc[mf][np * 2],     qlo[mf], khi[np]);
                    mma_bf16(acc[mf][np * 2 + 1], qlo[mf], khi[np] + 2);
                }
        }

        // ---- pad-mask + exp (fixed reference m = 0) ----
#pragma unroll
        for (int mf = 0; mf < 2; mf++) {
            float rs1 = 0.f, rs2 = 0.f;
#pragma unroll
            for (int nf = 0; nf < 8; nf++) {
                float2 mv = *(float2*)&mk[nf * 8 + (lane & 3) * 2];
                float p0 = __expf(acc[mf][nf][0] + mv.x);
                float p1 = __expf(acc[mf][nf][1] + mv.y);
                float p2 = __expf(acc[mf][nf][2] + mv.x);
                float p3 = __expf(acc[mf][nf][3] + mv.y);
                acc[mf][nf][0] = p0; acc[mf][nf][1] = p1;
                acc[mf][nf][2] = p2; acc[mf][nf][3] = p3;
                rs1 += p0 + p1;
                rs2 += p2 + p3;
            }
            rs1 += __shfl_xor_sync(0xffffffffu, rs1, 1);
            rs1 += __shfl_xor_sync(0xffffffffu, rs1, 2);
            rs2 += __shfl_xor_sync(0xffffffffu, rs2, 1);
            rs2 += __shfl_xor_sync(0xffffffffu, rs2, 2);
            l[mf][0] += rs1;
            l[mf][1] += rs2;
        }

        // ---- O += P V, pass-major (fast P split) ----
#pragma unroll
        for (int kf = 0; kf < 4; kf++) {
            uint32_t phi[2][4], plo[2][4];
#pragma unroll
            for (int mf = 0; mf < 2; mf++) {
                split2(acc[mf][2 * kf][0],     acc[mf][2 * kf][1],     phi[mf][0], plo[mf][0]);
                split2(acc[mf][2 * kf][2],     acc[mf][2 * kf][3],     phi[mf][1], plo[mf][1]);
                split2(acc[mf][2 * kf + 1][0], acc[mf][2 * kf + 1][1], phi[mf][2], plo[mf][2]);
                split2(acc[mf][2 * kf + 1][2], acc[mf][2 * kf + 1][3], phi[mf][3], plo[mf][3]);
            }
            uint32_t vhi[4][4], vlo[4][4];
#pragma unroll
            for (int np = 0; np < 4; np++) {
                int row = kf * 16 + (lane & 15);
                int col = (np * 2 + (lane >> 4)) * 8;
                uint32_t ad = sbase + st + (uint32_t)(row * 144 + col * 2);
                ldmatrix_x4_trans(vhi[np][0], vhi[np][1], vhi[np][2], vhi[np][3], ad + F_VH);
                ldmatrix_x4_trans(vlo[np][0], vlo[np][1], vlo[np][2], vlo[np][3], ad + F_VL);
            }
#pragma unroll
            for (int mf = 0; mf < 2; mf++)
#pragma unroll
                for (int np = 0; np < 4; np++) {
                    mma_bf16(o[mf][np * 2],     phi[mf], vhi[np]);
                    mma_bf16(o[mf][np * 2 + 1], phi[mf], vhi[np] + 2);
                }
#pragma unroll
            for (int mf = 0; mf < 2; mf++)
#pragma unroll
                for (int np = 0; np < 4; np++) {
                    mma_bf16(o[mf][np * 2],     phi[mf], vlo[np]);
                    mma_bf16(o[mf][np * 2 + 1], phi[mf], vlo[np] + 2);
                }
#pragma unroll
            for (int mf = 0; mf < 2; mf++)
#pragma unroll
                for (int np = 0; np < 4; np++) {
                    mma_bf16(o[mf][np * 2],     plo[mf], vhi[np]);
                    mma_bf16(o[mf][np * 2 + 1], plo[mf], vhi[np] + 2);
                }
        }
    }

    // ---- epilogue ----
#pragma unroll
    for (int mf = 0; mf < 2; mf++) {
        float inv1 = 1.f / l[mf][0];
        float inv2 = 1.f / l[mf][1];
        int t1 = q0 + qbase + mf * 16 + (lane >> 2);
        int t2 = t1 + 8;
#pragma unroll
        for (int nf = 0; nf < 8; nf++) {
            int d = h * 64 + nf * 8 + (lane & 3) * 2;
            size_t r1 = (size_t)(t1 * 2 + b) * E_DIM + d;
            size_t r2 = (size_t)(t2 * 2 + b) * E_DIM + d;
            uint32_t hw, lw;
            split2(o[mf][nf][0] * inv1, o[mf][nf][1] * inv1, hw, lw);
            *(uint32_t*)(attn_hi + r1) = hw;
            *(uint32_t*)(attn_lo + r1) = lw;
            split2(o[mf][nf][2] * inv2, o[mf][nf][3] * inv2, hw, lw);
            *(uint32_t*)(attn_hi + r2) = hw;
            *(uint32_t*)(attn_lo + r2) = lw;
        }
    }
}

// ===========================================================================
extern "C" void kernel_launch(void* const* d_in, const int* in_sizes, int n_in,
                              void* d_out, int out_size)
{
    const float* x      = (const float*)d_in[0];
    const float* w_in   = (const float*)d_in[1];
    const float* b_in   = (const float*)d_in[2];
    const float* w_out  = (const float*)d_in[3];
    const float* b_out  = (const float*)d_in[4];
    const void*  mask   = d_in[5];
    float* out = (float*)d_out;

    __nv_bfloat16 *x_hi, *x_lo, *win_hi, *win_lo, *wout_hi, *wout_lo;
    __nv_bfloat16 *q_hi, *q_lo, *kv_hi, *kv_lo, *attn_hi, *attn_lo;
    cudaGetSymbolAddress((void**)&x_hi, g_x_hi);
    cudaGetSymbolAddress((void**)&x_lo, g_x_lo);
    cudaGetSymbolAddress((void**)&win_hi, g_win_hi);
    cudaGetSymbolAddress((void**)&win_lo, g_win_lo);
    cudaGetSymbolAddress((void**)&wout_hi, g_wout_hi);
    cudaGetSymbolAddress((void**)&wout_lo, g_wout_lo);
    cudaGetSymbolAddress((void**)&q_hi, g_q_hi);
    cudaGetSymbolAddress((void**)&q_lo, g_q_lo);
    cudaGetSymbolAddress((void**)&kv_hi, g_kv_hi);
    cudaGetSymbolAddress((void**)&kv_lo, g_kv_lo);
    cudaGetSymbolAddress((void**)&attn_hi, g_attn_hi);
    cudaGetSymbolAddress((void**)&attn_lo, g_attn_lo);

    cudaFuncSetAttribute(gemm_dense,
                         cudaFuncAttributeMaxDynamicSharedMemorySize, G_TOTAL);
    cudaFuncSetAttribute(gemm_qkv,
                         cudaFuncAttributeMaxDynamicSharedMemorySize, G_TOTAL_RM);
    cudaFuncSetAttribute(flash_mma8,
                         cudaFuncAttributeMaxDynamicSharedMemorySize, F_TOTAL);

    // 0) combined prep: pre-split x/w_in/w_out + mask (one launch)
    prep_kernel<<<PREP_BLOCKS, 256>>>(x, w_in, w_out, mask,
                                      x_hi, x_lo, win_hi, win_lo,
                                      wout_hi, wout_lo);

    // 1) fused q + kv projection (q scaled 0.125; kv compacted)
    {
        dim3 grid(16 + 32, MROWS / 128);
        gemm_qkv<<<grid, 256, G_TOTAL_RM>>>(x_hi, x_lo, win_hi, win_lo, b_in,
                                            q_hi, q_lo, kv_hi, kv_lo);
    }

    // 2) flash attention (compacted, contiguous K/V) -> split bf16 attn
    {
        dim3 grid(T_DIM / 128, H_DIM, B_DIM);
        flash_mma8<<<grid, 128, F_TOTAL>>>(q_hi, q_lo, kv_hi, kv_lo,
                                           attn_hi, attn_lo);
    }

    // 3) out = attn @ W_out^T + b_out   [4096 x 1024] fp32
    {
        dim3 grid(E_DIM / 64, MROWS / 128);
        gemm_dense<<<grid, 256, G_TOTAL>>>(attn_hi, attn_lo,
                                           wout_hi, wout_lo,
                                           b_out, out, E_DIM);
    }
}